// round 8
// baseline (speedup 1.0000x reference)
#include <cuda_runtime.h>
#include <cuda_bf16.h>
#include <cstdint>

static constexpr int NN  = 8192;
static constexpr int EE  = 524288;
static constexpr int FIN = 128;
static constexpr int FH  = 256;
static constexpr int FO  = 128;
static constexpr int PAD = 192;   // padded CSR row stride (max degree ~98)

static constexpr int NT128  = NN / 128;                 // 64 tile rows
static constexpr int NTILES = NT128 * (NT128 + 1) / 2;  // 2080 upper-tri tiles
static constexpr int DGRID  = 152;                      // GB300 SM count

// z stored as e4m3 * 256; descale folded into sigmoid
static constexpr float ZSCALE   = 256.0f;
static constexpr float SIGSCALE = 0.5f / (ZSCALE * ZSCALE);

// ---------------- scratch (device globals; no allocation allowed) ----------
__device__ int   g_cnt[NN];
__device__ int   g_cursor[NN];       // zero at entry (BSS / reset by k_dinv)
__device__ int   g_src[NN * PAD];
__device__ float g_dinv[NN];
__device__ __nv_bfloat16 g_w1t[FH * FIN];
__device__ __nv_bfloat16 g_w2t[FO * FH];
__device__ __nv_bfloat16 g_hb[NN * FIN];
__device__ __nv_bfloat16 g_hab[NN * FIN];
__device__ __nv_bfloat16 g_a1b[NN * FH];
__device__ __nv_bfloat16 g_z2b[NN * FO];
__device__ uint16_t      g_z8[NN * 64];   // z in e4m3 pairs (128 fp8 / row)

// ---------------- weight prep ------------------------------------------------
__global__ void k_wconv(const float* __restrict__ W1, const float* __restrict__ W2) {
    int idx = blockIdx.x * blockDim.x + threadIdx.x;
    if (idx < FH * FIN) {
        int j = idx >> 7, k = idx & 127;
        g_w1t[idx] = __float2bfloat16(W1[k * FH + j]);
    } else {
        int i2 = idx - FH * FIN;
        int j = i2 >> 8, k = i2 & 255;
        g_w2t[i2] = __float2bfloat16(W2[k * FO + j]);
    }
}

// ---------------- embedding gather -------------------------------------------
__global__ void k_gather(const int* __restrict__ x, const float* __restrict__ emb) {
    int idx = blockIdx.x * blockDim.x + threadIdx.x;
    int n = idx >> 6, t = idx & 63;
    float2 f = *(const float2*)(emb + (size_t)x[n] * FIN + t * 2);
    ((__nv_bfloat162*)g_hb)[n * 64 + t] = __floats2bfloat162_rn(f.x, f.y);
}

// ---------------- single-pass padded CSR fill (8 edges / thread) --------------
__global__ void k_fill(const int* __restrict__ src, const int* __restrict__ dst) {
    int e = (blockIdx.x * blockDim.x + threadIdx.x) * 8;
    int4 d0 = *(const int4*)(dst + e);
    int4 d1 = *(const int4*)(dst + e + 4);
    int4 s0 = *(const int4*)(src + e);
    int4 s1 = *(const int4*)(src + e + 4);
    int p0 = atomicAdd(&g_cursor[d0.x], 1);
    int p1 = atomicAdd(&g_cursor[d0.y], 1);
    int p2 = atomicAdd(&g_cursor[d0.z], 1);
    int p3 = atomicAdd(&g_cursor[d0.w], 1);
    int p4 = atomicAdd(&g_cursor[d1.x], 1);
    int p5 = atomicAdd(&g_cursor[d1.y], 1);
    int p6 = atomicAdd(&g_cursor[d1.z], 1);
    int p7 = atomicAdd(&g_cursor[d1.w], 1);
    g_src[d0.x * PAD + p0] = s0.x;
    g_src[d0.y * PAD + p1] = s0.y;
    g_src[d0.z * PAD + p2] = s0.z;
    g_src[d0.w * PAD + p3] = s0.w;
    g_src[d1.x * PAD + p4] = s1.x;
    g_src[d1.y * PAD + p5] = s1.y;
    g_src[d1.z * PAD + p6] = s1.z;
    g_src[d1.w * PAD + p7] = s1.w;
}

__global__ void k_dinv() {
    int i = blockIdx.x * blockDim.x + threadIdx.x;
    int c = g_cursor[i];
    g_cnt[i]  = c;
    g_dinv[i] = rsqrtf((float)c + 1.0f);
    g_cursor[i] = 0;
}

// ---------------- layer-1 pre-aggregation over H ------------------------------
__global__ void __launch_bounds__(64) k_agg0() {
    const __nv_bfloat162* __restrict__ H = (const __nv_bfloat162*)g_hb;
    int d = blockIdx.x;
    int t = threadIdx.x;
    int cnt = g_cnt[d];
    const int* row = g_src + d * PAD;
    float ax = 0.f, ay = 0.f;
    int i = 0;
    for (; i + 4 <= cnt; i += 4) {
        int s0 = row[i], s1 = row[i + 1], s2 = row[i + 2], s3 = row[i + 3];
        float w0 = g_dinv[s0], w1 = g_dinv[s1], w2 = g_dinv[s2], w3 = g_dinv[s3];
        float2 f0 = __bfloat1622float2(H[s0 * 64 + t]);
        float2 f1 = __bfloat1622float2(H[s1 * 64 + t]);
        float2 f2 = __bfloat1622float2(H[s2 * 64 + t]);
        float2 f3 = __bfloat1622float2(H[s3 * 64 + t]);
        ax += w0 * f0.x + w1 * f1.x + w2 * f2.x + w3 * f3.x;
        ay += w0 * f0.y + w1 * f1.y + w2 * f2.y + w3 * f3.y;
    }
    for (; i < cnt; i++) {
        int s0 = row[i];
        float w0 = g_dinv[s0];
        float2 f0 = __bfloat1622float2(H[s0 * 64 + t]);
        ax += w0 * f0.x;
        ay += w0 * f0.y;
    }
    float dd = g_dinv[d];
    float2 hs = __bfloat1622float2(H[d * 64 + t]);
    float rx = fmaf(dd, ax, dd * dd * hs.x);
    float ry = fmaf(dd, ay, dd * dd * hs.y);
    ((__nv_bfloat162*)g_hab)[d * 64 + t] = __floats2bfloat162_rn(rx, ry);
}

// ---------------- shared mma helpers ------------------------------------------
__device__ __forceinline__ uint32_t smem_u32(const void* p) {
    return (uint32_t)__cvta_generic_to_shared(p);
}

__device__ __forceinline__ void ldmat4(uint32_t* r, const void* p) {
    asm volatile("ldmatrix.sync.aligned.m8n8.x4.shared.b16 {%0,%1,%2,%3}, [%4];"
                 : "=r"(r[0]), "=r"(r[1]), "=r"(r[2]), "=r"(r[3])
                 : "r"(smem_u32(p)));
}

__device__ __forceinline__ void mma16816(float* c, const uint32_t* a, const uint32_t* b) {
    asm volatile("mma.sync.aligned.m16n8k16.row.col.f32.bf16.bf16.f32 "
                 "{%0,%1,%2,%3}, {%4,%5,%6,%7}, {%8,%9}, {%0,%1,%2,%3};"
                 : "+f"(c[0]), "+f"(c[1]), "+f"(c[2]), "+f"(c[3])
                 : "r"(a[0]), "r"(a[1]), "r"(a[2]), "r"(a[3]), "r"(b[0]), "r"(b[1]));
}

__device__ __forceinline__ void mma16832f8(float* c, const uint32_t* a, const uint32_t* b) {
    asm volatile("mma.sync.aligned.m16n8k32.row.col.f32.e4m3.e4m3.f32 "
                 "{%0,%1,%2,%3}, {%4,%5,%6,%7}, {%8,%9}, {%0,%1,%2,%3};"
                 : "+f"(c[0]), "+f"(c[1]), "+f"(c[2]), "+f"(c[3])
                 : "r"(a[0]), "r"(a[1]), "r"(a[2]), "r"(a[3]), "r"(b[0]), "r"(b[1]));
}

// ---------------- lin1: a1 = relu( hab @ W1 + b1 ) ----------------------------
__global__ void __launch_bounds__(256) k_lin1(const float* __restrict__ b1) {
    constexpr int P = 136;
    extern __shared__ __nv_bfloat16 sm1[];
    __nv_bfloat16* sA = sm1;
    __nv_bfloat16* sB = sm1 + 64 * P;

    int t = threadIdx.x;
    int n0 = blockIdx.x * 64;

    for (int v = t; v < 1024; v += 256) {
        int r = v >> 4, m = v & 15;
        *(uint4*)&sA[r * P + m * 8] =
            *(const uint4*)&g_hab[(size_t)(n0 + r) * FIN + m * 8];
    }
    for (int v = t; v < 4096; v += 256) {
        int r = v >> 4, m = v & 15;
        *(uint4*)&sB[r * P + m * 8] = ((const uint4*)g_w1t)[v];
    }
    __syncthreads();

    int lane = t & 31, w = t >> 5;
    int wm = (w & 1) * 32, wn = (w >> 1) * 64;

    float acc[2][8][4] = {};
#pragma unroll
    for (int ks = 0; ks < 8; ks++) {
        int k0 = ks * 16;
        uint32_t a[2][4], b[8][2];
#pragma unroll
        for (int mt = 0; mt < 2; mt++)
            ldmat4(a[mt], sA + (wm + mt * 16 + (lane & 15)) * P + k0 + (lane >> 4) * 8);
#pragma unroll
        for (int pr = 0; pr < 4; pr++) {
            uint32_t r4[4];
            ldmat4(r4, sB + (wn + pr * 16 + (lane >> 4) * 8 + (lane & 7)) * P
                         + k0 + ((lane >> 3) & 1) * 8);
            b[2 * pr][0] = r4[0]; b[2 * pr][1] = r4[1];
            b[2 * pr + 1][0] = r4[2]; b[2 * pr + 1][1] = r4[3];
        }
#pragma unroll
        for (int mt = 0; mt < 2; mt++)
#pragma unroll
            for (int nt = 0; nt < 8; nt++) mma16816(acc[mt][nt], a[mt], b[nt]);
    }

#pragma unroll
    for (int mt = 0; mt < 2; mt++) {
        int row = wm + mt * 16 + (lane >> 2);
#pragma unroll
        for (int nt = 0; nt < 8; nt++) {
            int col = wn + nt * 8 + (lane & 3) * 2;
            float2 bb = *(const float2*)(b1 + col);
            float v0 = fmaxf(acc[mt][nt][0] + bb.x, 0.f);
            float v1 = fmaxf(acc[mt][nt][1] + bb.y, 0.f);
            float v2 = fmaxf(acc[mt][nt][2] + bb.x, 0.f);
            float v3 = fmaxf(acc[mt][nt][3] + bb.y, 0.f);
            *(__nv_bfloat162*)&g_a1b[(size_t)(n0 + row) * FH + col] =
                __floats2bfloat162_rn(v0, v1);
            *(__nv_bfloat162*)&g_a1b[(size_t)(n0 + row + 8) * FH + col] =
                __floats2bfloat162_rn(v2, v3);
        }
    }
}

// ---------------- lin2: g_z2b = bf16( a1 @ W2 ) --------------------------------
__global__ void __launch_bounds__(256) k_lin2() {
    constexpr int P = 264;
    extern __shared__ __nv_bfloat16 sm2[];
    __nv_bfloat16* sA = sm2;
    __nv_bfloat16* sB = sm2 + 64 * P;

    int t = threadIdx.x;
    int n0 = blockIdx.x * 64;

    for (int v = t; v < 2048; v += 256) {
        int r = v >> 5, m = v & 31;
        *(uint4*)&sA[r * P + m * 8] =
            *(const uint4*)&g_a1b[(size_t)(n0 + r) * FH + m * 8];
    }
    for (int v = t; v < 4096; v += 256) {
        int r = v >> 5, m = v & 31;
        *(uint4*)&sB[r * P + m * 8] = ((const uint4*)g_w2t)[v];
    }
    __syncthreads();

    int lane = t & 31, w = t >> 5;
    int wm = (w & 1) * 32, wn = (w >> 1) * 32;

    float acc[2][4][4] = {};
#pragma unroll
    for (int ks = 0; ks < 16; ks++) {
        int k0 = ks * 16;
        uint32_t a[2][4], b[4][2];
#pragma unroll
        for (int mt = 0; mt < 2; mt++)
            ldmat4(a[mt], sA + (wm + mt * 16 + (lane & 15)) * P + k0 + (lane >> 4) * 8);
#pragma unroll
        for (int pr = 0; pr < 2; pr++) {
            uint32_t r4[4];
            ldmat4(r4, sB + (wn + pr * 16 + (lane >> 4) * 8 + (lane & 7)) * P
                         + k0 + ((lane >> 3) & 1) * 8);
            b[2 * pr][0] = r4[0]; b[2 * pr][1] = r4[1];
            b[2 * pr + 1][0] = r4[2]; b[2 * pr + 1][1] = r4[3];
        }
#pragma unroll
        for (int mt = 0; mt < 2; mt++)
#pragma unroll
            for (int nt = 0; nt < 4; nt++) mma16816(acc[mt][nt], a[mt], b[nt]);
    }

#pragma unroll
    for (int mt = 0; mt < 2; mt++) {
        int row = wm + mt * 16 + (lane >> 2);
#pragma unroll
        for (int nt = 0; nt < 4; nt++) {
            int col = wn + nt * 8 + (lane & 3) * 2;
            *(__nv_bfloat162*)&g_z2b[(size_t)(n0 + row) * FO + col] =
                __floats2bfloat162_rn(acc[mt][nt][0], acc[mt][nt][1]);
            *(__nv_bfloat162*)&g_z2b[(size_t)(n0 + row + 8) * FO + col] =
                __floats2bfloat162_rn(acc[mt][nt][2], acc[mt][nt][3]);
        }
    }
}

// ---------------- GCN aggregation, layer 2 -> fp8 z ----------------------------
__global__ void __launch_bounds__(64) k_agg2(const float* __restrict__ bias) {
    const __nv_bfloat162* __restrict__ Z = (const __nv_bfloat162*)g_z2b;
    int d = blockIdx.x;
    int t = threadIdx.x;
    int cnt = g_cnt[d];
    const int* row = g_src + d * PAD;
    float ax = 0.f, ay = 0.f;
    int i = 0;
    for (; i + 4 <= cnt; i += 4) {
        int s0 = row[i], s1 = row[i + 1], s2 = row[i + 2], s3 = row[i + 3];
        float w0 = g_dinv[s0], w1 = g_dinv[s1], w2 = g_dinv[s2], w3 = g_dinv[s3];
        float2 f0 = __bfloat1622float2(Z[s0 * 64 + t]);
        float2 f1 = __bfloat1622float2(Z[s1 * 64 + t]);
        float2 f2 = __bfloat1622float2(Z[s2 * 64 + t]);
        float2 f3 = __bfloat1622float2(Z[s3 * 64 + t]);
        ax += w0 * f0.x + w1 * f1.x + w2 * f2.x + w3 * f3.x;
        ay += w0 * f0.y + w1 * f1.y + w2 * f2.y + w3 * f3.y;
    }
    for (; i < cnt; i++) {
        int s0 = row[i];
        float w0 = g_dinv[s0];
        float2 f0 = __bfloat1622float2(Z[s0 * 64 + t]);
        ax += w0 * f0.x;
        ay += w0 * f0.y;
    }
    float dd = g_dinv[d];
    float2 zs = __bfloat1622float2(Z[d * 64 + t]);
    float2 bb = ((const float2*)bias)[t];
    float rx = (fmaf(dd, ax, dd * dd * zs.x) + bb.x) * ZSCALE;
    float ry = (fmaf(dd, ay, dd * dd * zs.y) + bb.y) * ZSCALE;
    uint16_t pk;
    asm("cvt.rn.satfinite.e4m3x2.f32 %0, %1, %2;" : "=h"(pk) : "f"(ry), "f"(rx));
    g_z8[d * 64 + t] = pk;
}

// ---------------- decode: persistent, fp8 mma, pipelined bulk stores ----------
__device__ __forceinline__ float sigmoidf_(float v) {
    float th;
    asm("tanh.approx.f32 %0, %1;" : "=f"(th) : "f"(v * SIGSCALE));
    return fmaf(th, 0.5f, 0.5f);
}

__device__ __forceinline__ void bulk_store_row(void* gptr, uint32_t saddr, int bytes) {
    asm volatile("cp.async.bulk.global.shared::cta.bulk_group [%0], [%1], %2;"
                 :: "l"(gptr), "r"(saddr), "r"(bytes) : "memory");
}

__device__ __forceinline__ void tile_coords(int idx, int& bi, int& bj) {
    float fb = 64.5f - sqrtf(64.5f * 64.5f - 2.0f * (float)idx);
    int b = (int)fb;
    if (b < 0) b = 0;
    while (b > 0 && (b * 64 - b * (b - 1) / 2) > idx) b--;
    while (((b + 1) * 64 - (b + 1) * b / 2) <= idx) b++;
    bi = b;
    bj = b + (idx - (b * 64 - b * (b - 1) / 2));
}

// smem layout (bytes): [0, 69632) stage0 | [69632, 139264) stage1 |
//                      [139264, +36864) zbuf0 | [176128, +36864) zbuf1
static constexpr int STG_SZ  = 128 * 136 * 4;   // 69632
static constexpr int ZB_OFF  = 2 * STG_SZ;      // 139264
static constexpr int ZT_SZ   = 128 * 144;       // one z tile, pitch 144 B
static constexpr int ZB_SZ   = 2 * ZT_SZ;       // A + B tiles = 36864
static constexpr int DEC_SMEM = ZB_OFF + 2 * ZB_SZ;  // 212992

__device__ __forceinline__ void prefetch_z(char* smb, int zoff, int i0, int j0, int t) {
    const char* Z = (const char*)g_z8;
#pragma unroll
    for (int k = 0; k < 8; k++) {
        int v = t + k * 256;                // 0..2047
        int which = v >> 10;                // 0 = A(i0), 1 = B(j0)
        int r = (v >> 3) & 127;
        int c = (v & 7) * 16;
        const char* src = Z + (((size_t)((which ? j0 : i0) + r)) << 7) + c;
        uint32_t dst = smem_u32(smb + zoff + which * ZT_SZ + r * 144 + c);
        asm volatile("cp.async.cg.shared.global [%0], [%1], 16;"
                     :: "r"(dst), "l"(src) : "memory");
    }
}

__global__ void __launch_bounds__(256) k_decode(float* __restrict__ out) {
    extern __shared__ char smb[];
    int t = threadIdx.x;
    int lane = t & 31, w = t >> 5;
    int wm = (w & 3) * 32;
    int wn = (w >> 2) * 64;
    constexpr int PU = 72;   // z pitch in b16 units (144 B)
    constexpr int PF = 136;  // staging pitch in fp32

    // prefetch first tile
    {
        int bi, bj;
        tile_coords(blockIdx.x, bi, bj);
        prefetch_z(smb, ZB_OFF, bi * 128, bj * 128, t);
    }
    asm volatile("cp.async.commit_group;" ::: "memory");

    int cur = 0, sb = 0;
    for (int idx = blockIdx.x; idx < NTILES; idx += DGRID) {
        int bi, bj;
        tile_coords(idx, bi, bj);
        int i0 = bi * 128, j0 = bj * 128;
        bool diag = (bi == bj);

        int nxt = idx + DGRID;
        if (nxt < NTILES) {
            int nbi, nbj;
            tile_coords(nxt, nbi, nbj);
            prefetch_z(smb, ZB_OFF + (cur ^ 1) * ZB_SZ, nbi * 128, nbj * 128, t);
            asm volatile("cp.async.commit_group;" ::: "memory");
            asm volatile("cp.async.wait_group 1;" ::: "memory");
        } else {
            asm volatile("cp.async.wait_group 0;" ::: "memory");
        }
        __syncthreads();   // z[cur] ready

        const __nv_bfloat16* zA = (const __nv_bfloat16*)(smb + ZB_OFF + cur * ZB_SZ);
        const __nv_bfloat16* zB = zA + ZT_SZ / 2;   // ZT_SZ bytes / 2 = b16 units

        float acc[2][8][4] = {};
#pragma unroll
        for (int ks = 0; ks < 4; ks++) {
            int k0 = ks * 16;   // b16 units (= 32 fp8 per step)
            uint32_t a[2][4], b[8][2];
#pragma unroll
            for (int mt = 0; mt < 2; mt++)
                ldmat4(a[mt], zA + (wm + mt * 16 + (lane & 15)) * PU + k0 + (lane >> 4) * 8);
#pragma unroll
            for (int pr = 0; pr < 4; pr++) {
                uint32_t r4[4];
                ldmat4(r4, zB + (wn + pr * 16 + (lane >> 4) * 8 + (lane & 7)) * PU
                             + k0 + ((lane >> 3) & 1) * 8);
                b[2 * pr][0] = r4[0]; b[2 * pr][1] = r4[1];
                b[2 * pr + 1][0] = r4[2]; b[2 * pr + 1][1] = r4[3];
            }
#pragma unroll
            for (int mt = 0; mt < 2; mt++)
#pragma unroll
                for (int nt = 0; nt < 8; nt++) mma16832f8(acc[mt][nt], a[mt], b[nt]);
        }

#pragma unroll
        for (int mt = 0; mt < 2; mt++)
#pragma unroll
            for (int nt = 0; nt < 8; nt++)
#pragma unroll
                for (int q = 0; q < 4; q++) acc[mt][nt][q] = sigmoidf_(acc[mt][nt][q]);

        int r0b = wm + (lane >> 2);

        // ---- pass 1: direct tile ----
        if (t < 128) asm volatile("cp.async.bulk.wait_group.read 1;" ::: "memory");
        __syncthreads();   // stage[sb] free for everyone
        {
            float* sf = (float*)(smb + sb * STG_SZ);
#pragma unroll
            for (int mt = 0; mt < 2; mt++) {
                int r0 = r0b + mt * 16;
#pragma unroll
                for (int nt = 0; nt < 8; nt++) {
                    int c0 = wn + nt * 8 + (lane & 3) * 2;
                    *(float2*)&sf[r0 * PF + c0] =
                        make_float2(acc[mt][nt][0], acc[mt][nt][1]);
                    *(float2*)&sf[(r0 + 8) * PF + c0] =
                        make_float2(acc[mt][nt][2], acc[mt][nt][3]);
                }
            }
            __syncthreads();
            if (t < 128) {
                asm volatile("fence.proxy.async.shared::cta;" ::: "memory");
                bulk_store_row(out + (size_t)(i0 + t) * NN + j0,
                               smem_u32(&sf[t * PF]), 512);
                asm volatile("cp.async.bulk.commit_group;" ::: "memory");
            }
        }
        sb ^= 1;

        // ---- pass 2: mirror tile (transposed) ----
        if (!diag) {
            if (t < 128) asm volatile("cp.async.bulk.wait_group.read 1;" ::: "memory");
            __syncthreads();
            float* sf = (float*)(smb + sb * STG_SZ);
#pragma unroll
            for (int mt = 0; mt < 2; mt++) {
                int r0 = r0b + mt * 16;
#pragma unroll
                for (int nt = 0; nt < 8; nt++) {
                    int c0 = wn + nt * 8 + (lane & 3) * 2;
                    sf[c0 * PF + r0]           = acc[mt][nt][0];
                    sf[(c0 + 1) * PF + r0]     = acc[mt][nt][1];
                    sf[c0 * PF + r0 + 8]       = acc[mt][nt][2];
                    sf[(c0 + 1) * PF + r0 + 8] = acc[mt][nt][3];
                }
            }
            __syncthreads();
            if (t < 128) {
                asm volatile("fence.proxy.async.shared::cta;" ::: "memory");
                bulk_store_row(out + (size_t)(j0 + t) * NN + i0,
                               smem_u32(&sf[t * PF]), 512);
                asm volatile("cp.async.bulk.commit_group;" ::: "memory");
            }
            sb ^= 1;
        }

        cur ^= 1;
    }

    // drain all bulk stores before exit
    if (t < 128) asm volatile("cp.async.bulk.wait_group 0;" ::: "memory");
}

// ---------------- launch --------------------------------------------------------
extern "C" void kernel_launch(void* const* d_in, const int* in_sizes, int n_in,
                              void* d_out, int out_size) {
    const int*   x   = (const int*)d_in[0];
    const int*   ei  = (const int*)d_in[1];   // [2, E]: src then dst
    const float* emb = (const float*)d_in[2];
    const float* W1  = (const float*)d_in[3];
    const float* b1  = (const float*)d_in[4];
    const float* W2  = (const float*)d_in[5];
    const float* b2  = (const float*)d_in[6];
    float* out = (float*)d_out;

    const int* src = ei;
    const int* dst = ei + EE;

    const int smem_lin1 = (64 + 256) * 136 * (int)sizeof(__nv_bfloat16); // 87040
    const int smem_lin2 = (64 + 128) * 264 * (int)sizeof(__nv_bfloat16); // 101376
    cudaFuncSetAttribute(k_decode, cudaFuncAttributeMaxDynamicSharedMemorySize, DEC_SMEM);
    cudaFuncSetAttribute(k_lin1,   cudaFuncAttributeMaxDynamicSharedMemorySize, smem_lin1);
    cudaFuncSetAttribute(k_lin2,   cudaFuncAttributeMaxDynamicSharedMemorySize, smem_lin2);

    k_wconv <<<256, 256>>>(W1, W2);
    k_gather<<<NN * 64 / 256, 256>>>(x, emb);
    k_fill  <<<EE / 2048, 256>>>(src, dst);
    k_dinv  <<<NN / 256, 256>>>();

    k_agg0<<<NN, 64>>>();
    k_lin1<<<NN / 64, 256, smem_lin1>>>(b1);
    k_lin2<<<NN / 64, 256, smem_lin2>>>();
    k_agg2<<<NN, 64>>>(b2);

    k_decode<<<DGRID, 256, DEC_SMEM>>>(out);
}

// round 9
// speedup vs baseline: 1.1854x; 1.1854x over previous
#include <cuda_runtime.h>
#include <cuda_bf16.h>
#include <cstdint>

static constexpr int NN  = 8192;
static constexpr int EE  = 524288;
static constexpr int FIN = 128;
static constexpr int FH  = 256;
static constexpr int FO  = 128;
static constexpr int PAD = 192;   // padded CSR row stride (max degree ~98)

static constexpr int NT128  = NN / 128;
static constexpr int NTILES = NT128 * (NT128 + 1) / 2;  // 2080
static constexpr int DGRID  = 304;                      // 2 CTAs / SM

static constexpr float ZSCALE   = 256.0f;
static constexpr float SIGSCALE = 0.5f / (ZSCALE * ZSCALE);

// ---------------- scratch ----------------------------------------------------
__device__ int g_cursor[NN];       // degree counter; reset by k_decode each run
__device__ int g_src[NN * PAD];
__device__ __nv_bfloat16 g_w1t[FH * FIN];
__device__ __nv_bfloat16 g_w2t[FO * FH];
__device__ __nv_bfloat16 g_hb[NN * FIN];
__device__ __nv_bfloat16 g_hab[NN * FIN];
__device__ __nv_bfloat16 g_a1b[NN * FH];
__device__ __nv_bfloat16 g_z2b[NN * FO];
__device__ uint16_t      g_z8[NN * 64];   // z as e4m3 pairs

// ---------------- fused prep: wconv | gather | CSR fill ----------------------
__global__ void k_prep(const int* __restrict__ x, const float* __restrict__ emb,
                       const float* __restrict__ W1, const float* __restrict__ W2,
                       const int* __restrict__ src, const int* __restrict__ dst) {
    int b = blockIdx.x;
    if (b < 2048) {                       // embedding gather (NN*64 threads)
        int idx = b * 256 + threadIdx.x;
        int n = idx >> 6, t = idx & 63;
        float2 f = *(const float2*)(emb + (size_t)x[n] * FIN + t * 2);
        ((__nv_bfloat162*)g_hb)[n * 64 + t] = __floats2bfloat162_rn(f.x, f.y);
    } else if (b < 2048 + 256) {          // weight transpose + bf16
        int idx = (b - 2048) * 256 + threadIdx.x;
        if (idx < FH * FIN) {
            int j = idx >> 7, k = idx & 127;
            g_w1t[idx] = __float2bfloat16(W1[k * FH + j]);
        } else {
            int i2 = idx - FH * FIN;
            int j = i2 >> 8, k = i2 & 255;
            g_w2t[i2] = __float2bfloat16(W2[k * FO + j]);
        }
    } else {                              // padded CSR fill, 8 edges/thread
        int e = ((b - 2304) * 256 + threadIdx.x) * 8;
        int4 d0 = *(const int4*)(dst + e);
        int4 d1 = *(const int4*)(dst + e + 4);
        int4 s0 = *(const int4*)(src + e);
        int4 s1 = *(const int4*)(src + e + 4);
        int p0 = atomicAdd(&g_cursor[d0.x], 1);
        int p1 = atomicAdd(&g_cursor[d0.y], 1);
        int p2 = atomicAdd(&g_cursor[d0.z], 1);
        int p3 = atomicAdd(&g_cursor[d0.w], 1);
        int p4 = atomicAdd(&g_cursor[d1.x], 1);
        int p5 = atomicAdd(&g_cursor[d1.y], 1);
        int p6 = atomicAdd(&g_cursor[d1.z], 1);
        int p7 = atomicAdd(&g_cursor[d1.w], 1);
        g_src[d0.x * PAD + p0] = s0.x;
        g_src[d0.y * PAD + p1] = s0.y;
        g_src[d0.z * PAD + p2] = s0.z;
        g_src[d0.w * PAD + p3] = s0.w;
        g_src[d1.x * PAD + p4] = s1.x;
        g_src[d1.y * PAD + p5] = s1.y;
        g_src[d1.z * PAD + p6] = s1.z;
        g_src[d1.w * PAD + p7] = s1.w;
    }
}

// ---------------- layer-1 pre-aggregation (smem idx+weight preload) ----------
__global__ void __launch_bounds__(64) k_agg0() {
    __shared__ int   sidx[PAD];
    __shared__ float swt[PAD];
    const __nv_bfloat162* __restrict__ H = (const __nv_bfloat162*)g_hb;
    int d = blockIdx.x;
    int t = threadIdx.x;
    int cnt = g_cursor[d];
    const int* row = g_src + d * PAD;
    for (int i = t; i < cnt; i += 64) {
        int s = row[i];
        sidx[i] = s;
        swt[i]  = rsqrtf((float)g_cursor[s] + 1.0f);
    }
    __syncthreads();
    float ax = 0.f, ay = 0.f;
    int i = 0;
    for (; i + 4 <= cnt; i += 4) {
        int s0 = sidx[i], s1 = sidx[i + 1], s2 = sidx[i + 2], s3 = sidx[i + 3];
        float w0 = swt[i], w1 = swt[i + 1], w2 = swt[i + 2], w3 = swt[i + 3];
        float2 f0 = __bfloat1622float2(H[s0 * 64 + t]);
        float2 f1 = __bfloat1622float2(H[s1 * 64 + t]);
        float2 f2 = __bfloat1622float2(H[s2 * 64 + t]);
        float2 f3 = __bfloat1622float2(H[s3 * 64 + t]);
        ax += w0 * f0.x + w1 * f1.x + w2 * f2.x + w3 * f3.x;
        ay += w0 * f0.y + w1 * f1.y + w2 * f2.y + w3 * f3.y;
    }
    for (; i < cnt; i++) {
        int s0 = sidx[i];
        float w0 = swt[i];
        float2 f0 = __bfloat1622float2(H[s0 * 64 + t]);
        ax += w0 * f0.x;
        ay += w0 * f0.y;
    }
    float dd = rsqrtf((float)cnt + 1.0f);
    float2 hs = __bfloat1622float2(H[d * 64 + t]);
    float rx = fmaf(dd, ax, dd * dd * hs.x);
    float ry = fmaf(dd, ay, dd * dd * hs.y);
    ((__nv_bfloat162*)g_hab)[d * 64 + t] = __floats2bfloat162_rn(rx, ry);
}

// ---------------- shared mma helpers ------------------------------------------
__device__ __forceinline__ uint32_t smem_u32(const void* p) {
    return (uint32_t)__cvta_generic_to_shared(p);
}

__device__ __forceinline__ void ldmat4(uint32_t* r, const void* p) {
    asm volatile("ldmatrix.sync.aligned.m8n8.x4.shared.b16 {%0,%1,%2,%3}, [%4];"
                 : "=r"(r[0]), "=r"(r[1]), "=r"(r[2]), "=r"(r[3])
                 : "r"(smem_u32(p)));
}

__device__ __forceinline__ void mma16816(float* c, const uint32_t* a, const uint32_t* b) {
    asm volatile("mma.sync.aligned.m16n8k16.row.col.f32.bf16.bf16.f32 "
                 "{%0,%1,%2,%3}, {%4,%5,%6,%7}, {%8,%9}, {%0,%1,%2,%3};"
                 : "+f"(c[0]), "+f"(c[1]), "+f"(c[2]), "+f"(c[3])
                 : "r"(a[0]), "r"(a[1]), "r"(a[2]), "r"(a[3]), "r"(b[0]), "r"(b[1]));
}

__device__ __forceinline__ void mma16832f8(float* c, const uint32_t* a, const uint32_t* b) {
    asm volatile("mma.sync.aligned.m16n8k32.row.col.f32.e4m3.e4m3.f32 "
                 "{%0,%1,%2,%3}, {%4,%5,%6,%7}, {%8,%9}, {%0,%1,%2,%3};"
                 : "+f"(c[0]), "+f"(c[1]), "+f"(c[2]), "+f"(c[3])
                 : "r"(a[0]), "r"(a[1]), "r"(a[2]), "r"(a[3]), "r"(b[0]), "r"(b[1]));
}

// ---------------- lin1: a1 = relu( hab @ W1 + b1 ) ----------------------------
__global__ void __launch_bounds__(256) k_lin1(const float* __restrict__ b1) {
    constexpr int P = 136;
    extern __shared__ __nv_bfloat16 sm1[];
    __nv_bfloat16* sA = sm1;
    __nv_bfloat16* sB = sm1 + 64 * P;

    int t = threadIdx.x;
    int n0 = blockIdx.x * 64;

    for (int v = t; v < 1024; v += 256) {
        int r = v >> 4, m = v & 15;
        *(uint4*)&sA[r * P + m * 8] =
            *(const uint4*)&g_hab[(size_t)(n0 + r) * FIN + m * 8];
    }
    for (int v = t; v < 4096; v += 256) {
        int r = v >> 4, m = v & 15;
        *(uint4*)&sB[r * P + m * 8] = ((const uint4*)g_w1t)[v];
    }
    __syncthreads();

    int lane = t & 31, w = t >> 5;
    int wm = (w & 1) * 32, wn = (w >> 1) * 64;

    float acc[2][8][4] = {};
#pragma unroll
    for (int ks = 0; ks < 8; ks++) {
        int k0 = ks * 16;
        uint32_t a[2][4], b[8][2];
#pragma unroll
        for (int mt = 0; mt < 2; mt++)
            ldmat4(a[mt], sA + (wm + mt * 16 + (lane & 15)) * P + k0 + (lane >> 4) * 8);
#pragma unroll
        for (int pr = 0; pr < 4; pr++) {
            uint32_t r4[4];
            ldmat4(r4, sB + (wn + pr * 16 + (lane >> 4) * 8 + (lane & 7)) * P
                         + k0 + ((lane >> 3) & 1) * 8);
            b[2 * pr][0] = r4[0]; b[2 * pr][1] = r4[1];
            b[2 * pr + 1][0] = r4[2]; b[2 * pr + 1][1] = r4[3];
        }
#pragma unroll
        for (int mt = 0; mt < 2; mt++)
#pragma unroll
            for (int nt = 0; nt < 8; nt++) mma16816(acc[mt][nt], a[mt], b[nt]);
    }

#pragma unroll
    for (int mt = 0; mt < 2; mt++) {
        int row = wm + mt * 16 + (lane >> 2);
#pragma unroll
        for (int nt = 0; nt < 8; nt++) {
            int col = wn + nt * 8 + (lane & 3) * 2;
            float2 bb = *(const float2*)(b1 + col);
            float v0 = fmaxf(acc[mt][nt][0] + bb.x, 0.f);
            float v1 = fmaxf(acc[mt][nt][1] + bb.y, 0.f);
            float v2 = fmaxf(acc[mt][nt][2] + bb.x, 0.f);
            float v3 = fmaxf(acc[mt][nt][3] + bb.y, 0.f);
            *(__nv_bfloat162*)&g_a1b[(size_t)(n0 + row) * FH + col] =
                __floats2bfloat162_rn(v0, v1);
            *(__nv_bfloat162*)&g_a1b[(size_t)(n0 + row + 8) * FH + col] =
                __floats2bfloat162_rn(v2, v3);
        }
    }
}

// ---------------- lin2: g_z2b = bf16( a1 @ W2 ) --------------------------------
__global__ void __launch_bounds__(256) k_lin2() {
    constexpr int P = 264;
    extern __shared__ __nv_bfloat16 sm2[];
    __nv_bfloat16* sA = sm2;
    __nv_bfloat16* sB = sm2 + 64 * P;

    int t = threadIdx.x;
    int n0 = blockIdx.x * 64;

    for (int v = t; v < 2048; v += 256) {
        int r = v >> 5, m = v & 31;
        *(uint4*)&sA[r * P + m * 8] =
            *(const uint4*)&g_a1b[(size_t)(n0 + r) * FH + m * 8];
    }
    for (int v = t; v < 4096; v += 256) {
        int r = v >> 5, m = v & 31;
        *(uint4*)&sB[r * P + m * 8] = ((const uint4*)g_w2t)[v];
    }
    __syncthreads();

    int lane = t & 31, w = t >> 5;
    int wm = (w & 1) * 32, wn = (w >> 1) * 32;

    float acc[2][4][4] = {};
#pragma unroll
    for (int ks = 0; ks < 16; ks++) {
        int k0 = ks * 16;
        uint32_t a[2][4], b[4][2];
#pragma unroll
        for (int mt = 0; mt < 2; mt++)
            ldmat4(a[mt], sA + (wm + mt * 16 + (lane & 15)) * P + k0 + (lane >> 4) * 8);
#pragma unroll
        for (int pr = 0; pr < 2; pr++) {
            uint32_t r4[4];
            ldmat4(r4, sB + (wn + pr * 16 + (lane >> 4) * 8 + (lane & 7)) * P
                         + k0 + ((lane >> 3) & 1) * 8);
            b[2 * pr][0] = r4[0]; b[2 * pr][1] = r4[1];
            b[2 * pr + 1][0] = r4[2]; b[2 * pr + 1][1] = r4[3];
        }
#pragma unroll
        for (int mt = 0; mt < 2; mt++)
#pragma unroll
            for (int nt = 0; nt < 4; nt++) mma16816(acc[mt][nt], a[mt], b[nt]);
    }

#pragma unroll
    for (int mt = 0; mt < 2; mt++) {
        int row = wm + mt * 16 + (lane >> 2);
#pragma unroll
        for (int nt = 0; nt < 4; nt++) {
            int col = wn + nt * 8 + (lane & 3) * 2;
            *(__nv_bfloat162*)&g_z2b[(size_t)(n0 + row) * FO + col] =
                __floats2bfloat162_rn(acc[mt][nt][0], acc[mt][nt][1]);
            *(__nv_bfloat162*)&g_z2b[(size_t)(n0 + row + 8) * FO + col] =
                __floats2bfloat162_rn(acc[mt][nt][2], acc[mt][nt][3]);
        }
    }
}

// ---------------- GCN aggregation, layer 2 -> fp8 z ----------------------------
__global__ void __launch_bounds__(64) k_agg2(const float* __restrict__ bias) {
    __shared__ int   sidx[PAD];
    __shared__ float swt[PAD];
    const __nv_bfloat162* __restrict__ Z = (const __nv_bfloat162*)g_z2b;
    int d = blockIdx.x;
    int t = threadIdx.x;
    int cnt = g_cursor[d];
    const int* row = g_src + d * PAD;
    for (int i = t; i < cnt; i += 64) {
        int s = row[i];
        sidx[i] = s;
        swt[i]  = rsqrtf((float)g_cursor[s] + 1.0f);
    }
    __syncthreads();
    float ax = 0.f, ay = 0.f;
    int i = 0;
    for (; i + 4 <= cnt; i += 4) {
        int s0 = sidx[i], s1 = sidx[i + 1], s2 = sidx[i + 2], s3 = sidx[i + 3];
        float w0 = swt[i], w1 = swt[i + 1], w2 = swt[i + 2], w3 = swt[i + 3];
        float2 f0 = __bfloat1622float2(Z[s0 * 64 + t]);
        float2 f1 = __bfloat1622float2(Z[s1 * 64 + t]);
        float2 f2 = __bfloat1622float2(Z[s2 * 64 + t]);
        float2 f3 = __bfloat1622float2(Z[s3 * 64 + t]);
        ax += w0 * f0.x + w1 * f1.x + w2 * f2.x + w3 * f3.x;
        ay += w0 * f0.y + w1 * f1.y + w2 * f2.y + w3 * f3.y;
    }
    for (; i < cnt; i++) {
        int s0 = sidx[i];
        float w0 = swt[i];
        float2 f0 = __bfloat1622float2(Z[s0 * 64 + t]);
        ax += w0 * f0.x;
        ay += w0 * f0.y;
    }
    float dd = rsqrtf((float)cnt + 1.0f);
    float2 zs = __bfloat1622float2(Z[d * 64 + t]);
    float2 bb = ((const float2*)bias)[t];
    float rx = (fmaf(dd, ax, dd * dd * zs.x) + bb.x) * ZSCALE;
    float ry = (fmaf(dd, ay, dd * dd * zs.y) + bb.y) * ZSCALE;
    uint16_t pk;
    asm("cvt.rn.satfinite.e4m3x2.f32 %0, %1, %2;" : "=h"(pk) : "f"(ry), "f"(rx));
    g_z8[d * 64 + t] = pk;
}

// ---------------- decode: persistent fp8 mma, occ 2, single-buffer -------------
__device__ __forceinline__ float sigmoidf_(float v) {
    float th;
    asm("tanh.approx.f32 %0, %1;" : "=f"(th) : "f"(v * SIGSCALE));
    return fmaf(th, 0.5f, 0.5f);
}

__device__ __forceinline__ void bulk_store_row(void* gptr, uint32_t saddr, int bytes) {
    asm volatile("cp.async.bulk.global.shared::cta.bulk_group [%0], [%1], %2;"
                 :: "l"(gptr), "r"(saddr), "r"(bytes) : "memory");
}

__device__ __forceinline__ void tile_coords(int idx, int& bi, int& bj) {
    float fb = 64.5f - sqrtf(64.5f * 64.5f - 2.0f * (float)idx);
    int b = (int)fb;
    if (b < 0) b = 0;
    while (b > 0 && (b * 64 - b * (b - 1) / 2) > idx) b--;
    while (((b + 1) * 64 - (b + 1) * b / 2) <= idx) b++;
    bi = b;
    bj = b + (idx - (b * 64 - b * (b - 1) / 2));
}

// smem: [0, 69632) fp32 staging | [69632, +36864) z tiles (A then B, pitch 144)
static constexpr int STG_SZ   = 128 * 136 * 4;      // 69632
static constexpr int ZB_OFF   = STG_SZ;
static constexpr int ZT_SZ    = 128 * 144;          // 18432
static constexpr int DEC_SMEM = STG_SZ + 2 * ZT_SZ; // 106496 -> 2 CTAs/SM

__global__ void __launch_bounds__(256, 2) k_decode(float* __restrict__ out) {
    extern __shared__ char smb[];
    int t = threadIdx.x;
    int lane = t & 31, w = t >> 5;
    int wm = (w & 3) * 32;
    int wn = (w >> 2) * 64;
    constexpr int PU = 72;   // z pitch in b16 units (144 B)
    constexpr int PF = 136;  // staging pitch in fp32

    // reset CSR cursors for the next graph replay (we run after agg2)
    if (blockIdx.x < 32) g_cursor[blockIdx.x * 256 + t] = 0;

    float* sf = (float*)smb;
    const __nv_bfloat16* zA = (const __nv_bfloat16*)(smb + ZB_OFF);
    const __nv_bfloat16* zB = zA + ZT_SZ / 2;

    for (int idx = blockIdx.x; idx < NTILES; idx += DGRID) {
        int bi, bj;
        tile_coords(idx, bi, bj);
        int i0 = bi * 128, j0 = bj * 128;
        bool diag = (bi == bj);

        // ldmatrix of the previous tile finished before last staging barriers;
        // safe to overwrite z tiles now.
        {
            const char* Z = (const char*)g_z8;
#pragma unroll
            for (int k = 0; k < 8; k++) {
                int v = t + k * 256;
                int which = v >> 10;
                int r = (v >> 3) & 127;
                int c = (v & 7) * 16;
                const char* srcp = Z + (((size_t)((which ? j0 : i0) + r)) << 7) + c;
                uint32_t dstp = smem_u32(smb + ZB_OFF + which * ZT_SZ + r * 144 + c);
                asm volatile("cp.async.cg.shared.global [%0], [%1], 16;"
                             :: "r"(dstp), "l"(srcp) : "memory");
            }
        }
        asm volatile("cp.async.commit_group;" ::: "memory");
        asm volatile("cp.async.wait_group 0;" ::: "memory");
        __syncthreads();

        float acc[2][8][4] = {};
#pragma unroll
        for (int ks = 0; ks < 4; ks++) {
            int k0 = ks * 16;
            uint32_t a[2][4], b[8][2];
#pragma unroll
            for (int mt = 0; mt < 2; mt++)
                ldmat4(a[mt], zA + (wm + mt * 16 + (lane & 15)) * PU + k0 + (lane >> 4) * 8);
#pragma unroll
            for (int pr = 0; pr < 4; pr++) {
                uint32_t r4[4];
                ldmat4(r4, zB + (wn + pr * 16 + (lane >> 4) * 8 + (lane & 7)) * PU
                             + k0 + ((lane >> 3) & 1) * 8);
                b[2 * pr][0] = r4[0]; b[2 * pr][1] = r4[1];
                b[2 * pr + 1][0] = r4[2]; b[2 * pr + 1][1] = r4[3];
            }
#pragma unroll
            for (int mt = 0; mt < 2; mt++)
#pragma unroll
                for (int nt = 0; nt < 8; nt++) mma16832f8(acc[mt][nt], a[mt], b[nt]);
        }

#pragma unroll
        for (int mt = 0; mt < 2; mt++)
#pragma unroll
            for (int nt = 0; nt < 8; nt++)
#pragma unroll
                for (int q = 0; q < 4; q++) acc[mt][nt][q] = sigmoidf_(acc[mt][nt][q]);

        int r0b = wm + (lane >> 2);

        // ---- pass 1: direct tile ----
        asm volatile("cp.async.bulk.wait_group.read 0;" ::: "memory");
        __syncthreads();
#pragma unroll
        for (int mt = 0; mt < 2; mt++) {
            int r0 = r0b + mt * 16;
#pragma unroll
            for (int nt = 0; nt < 8; nt++) {
                int c0 = wn + nt * 8 + (lane & 3) * 2;
                *(float2*)&sf[r0 * PF + c0] =
                    make_float2(acc[mt][nt][0], acc[mt][nt][1]);
                *(float2*)&sf[(r0 + 8) * PF + c0] =
                    make_float2(acc[mt][nt][2], acc[mt][nt][3]);
            }
        }
        __syncthreads();
        if (t < 128) {
            asm volatile("fence.proxy.async.shared::cta;" ::: "memory");
            bulk_store_row(out + (size_t)(i0 + t) * NN + j0, smem_u32(&sf[t * PF]), 512);
            asm volatile("cp.async.bulk.commit_group;" ::: "memory");
        }

        // ---- pass 2: mirror tile (transposed) ----
        if (!diag) {
            asm volatile("cp.async.bulk.wait_group.read 0;" ::: "memory");
            __syncthreads();
#pragma unroll
            for (int mt = 0; mt < 2; mt++) {
                int r0 = r0b + mt * 16;
#pragma unroll
                for (int nt = 0; nt < 8; nt++) {
                    int c0 = wn + nt * 8 + (lane & 3) * 2;
                    sf[c0 * PF + r0]           = acc[mt][nt][0];
                    sf[(c0 + 1) * PF + r0]     = acc[mt][nt][1];
                    sf[c0 * PF + r0 + 8]       = acc[mt][nt][2];
                    sf[(c0 + 1) * PF + r0 + 8] = acc[mt][nt][3];
                }
            }
            __syncthreads();
            if (t < 128) {
                asm volatile("fence.proxy.async.shared::cta;" ::: "memory");
                bulk_store_row(out + (size_t)(j0 + t) * NN + i0, smem_u32(&sf[t * PF]), 512);
                asm volatile("cp.async.bulk.commit_group;" ::: "memory");
            }
        }
    }

    asm volatile("cp.async.bulk.wait_group 0;" ::: "memory");
}

// ---------------- launch --------------------------------------------------------
extern "C" void kernel_launch(void* const* d_in, const int* in_sizes, int n_in,
                              void* d_out, int out_size) {
    const int*   x   = (const int*)d_in[0];
    const int*   ei  = (const int*)d_in[1];
    const float* emb = (const float*)d_in[2];
    const float* W1  = (const float*)d_in[3];
    const float* b1  = (const float*)d_in[4];
    const float* W2  = (const float*)d_in[5];
    const float* b2  = (const float*)d_in[6];
    float* out = (float*)d_out;

    const int* src = ei;
    const int* dst = ei + EE;

    const int smem_lin1 = (64 + 256) * 136 * (int)sizeof(__nv_bfloat16); // 87040
    const int smem_lin2 = (64 + 128) * 264 * (int)sizeof(__nv_bfloat16); // 101376
    cudaFuncSetAttribute(k_decode, cudaFuncAttributeMaxDynamicSharedMemorySize, DEC_SMEM);
    cudaFuncSetAttribute(k_lin1,   cudaFuncAttributeMaxDynamicSharedMemorySize, smem_lin1);
    cudaFuncSetAttribute(k_lin2,   cudaFuncAttributeMaxDynamicSharedMemorySize, smem_lin2);

    k_prep<<<2560, 256>>>(x, emb, W1, W2, src, dst);
    k_agg0<<<NN, 64>>>();
    k_lin1<<<NN / 64, 256, smem_lin1>>>(b1);
    k_lin2<<<NN / 64, 256, smem_lin2>>>();
    k_agg2<<<NN, 64>>>(b2);
    k_decode<<<DGRID, 256, DEC_SMEM>>>(out);
}

// round 10
// speedup vs baseline: 1.2762x; 1.0766x over previous
#include <cuda_runtime.h>
#include <cuda_bf16.h>
#include <cuda_fp16.h>
#include <cstdint>

static constexpr int NN  = 8192;
static constexpr int EE  = 524288;
static constexpr int FIN = 128;
static constexpr int FH  = 256;
static constexpr int FO  = 128;
static constexpr int PAD = 192;   // padded CSR row stride (max degree ~98)

static constexpr int NT128  = NN / 128;
static constexpr int NTILES = NT128 * (NT128 + 1) / 2;  // 2080
static constexpr int DGRID  = 304;                      // 2 CTAs / SM

static constexpr float HSCALE  = 512.0f;    // h  stored as e4m3 * 512
static constexpr float Z2SCALE = 4096.0f;   // z2 stored as e4m3 * 4096
static constexpr float ZSCALE  = 256.0f;    // z  stored as e4m3 * 256
static constexpr float SIGSCALE = 0.5f / (ZSCALE * ZSCALE);

// ---------------- scratch ----------------------------------------------------
__device__ int g_cursor[NN];       // degree counter; reset by k_decode each run
__device__ int g_src[NN * PAD];
__device__ __nv_bfloat16 g_w1t[FH * FIN];
__device__ __nv_bfloat16 g_w2t[FO * FH];
__device__ uint16_t      g_h8[NN * 64];    // h  as e4m3 pairs (*HSCALE)
__device__ __nv_bfloat16 g_hab[NN * FIN];  // aggregated h (bf16)
__device__ uint16_t      g_z28[NN * 64];   // z2 as e4m3 pairs (*Z2SCALE)
__device__ uint16_t      g_z8[NN * 64];    // z  as e4m3 pairs (*ZSCALE)

// ---------------- helpers ------------------------------------------------------
__device__ __forceinline__ uint32_t smem_u32(const void* p) {
    return (uint32_t)__cvta_generic_to_shared(p);
}

__device__ __forceinline__ float2 fp8x2_to_float2(uint16_t pk) {
    uint32_t h2;
    asm("cvt.rn.f16x2.e4m3x2 %0, %1;" : "=r"(h2) : "h"(pk));
    __half2 hh = *reinterpret_cast<__half2*>(&h2);
    return __half22float2(hh);
}

__device__ __forceinline__ uint16_t float2_to_fp8x2(float lo, float hi) {
    uint16_t pk;
    asm("cvt.rn.satfinite.e4m3x2.f32 %0, %1, %2;" : "=h"(pk) : "f"(hi), "f"(lo));
    return pk;
}

// ---------------- fused prep: wconv | gather(fp8) | CSR fill -------------------
__global__ void k_prep(const int* __restrict__ x, const float* __restrict__ emb,
                       const float* __restrict__ W1, const float* __restrict__ W2,
                       const int* __restrict__ src, const int* __restrict__ dst) {
    int b = blockIdx.x;
    if (b < 2048) {                       // embedding gather -> fp8*HSCALE
        int idx = b * 256 + threadIdx.x;
        int n = idx >> 6, t = idx & 63;
        float2 f = *(const float2*)(emb + (size_t)x[n] * FIN + t * 2);
        g_h8[n * 64 + t] = float2_to_fp8x2(f.x * HSCALE, f.y * HSCALE);
    } else if (b < 2048 + 256) {          // weight transpose + bf16
        int idx = (b - 2048) * 256 + threadIdx.x;
        if (idx < FH * FIN) {
            int j = idx >> 7, k = idx & 127;
            g_w1t[idx] = __float2bfloat16(W1[k * FH + j]);
        } else {
            int i2 = idx - FH * FIN;
            int j = i2 >> 8, k = i2 & 255;
            g_w2t[i2] = __float2bfloat16(W2[k * FO + j]);
        }
    } else {                              // padded CSR fill, 8 edges/thread
        int e = ((b - 2304) * 256 + threadIdx.x) * 8;
        int4 d0 = *(const int4*)(dst + e);
        int4 d1 = *(const int4*)(dst + e + 4);
        int4 s0 = *(const int4*)(src + e);
        int4 s1 = *(const int4*)(src + e + 4);
        int p0 = atomicAdd(&g_cursor[d0.x], 1);
        int p1 = atomicAdd(&g_cursor[d0.y], 1);
        int p2 = atomicAdd(&g_cursor[d0.z], 1);
        int p3 = atomicAdd(&g_cursor[d0.w], 1);
        int p4 = atomicAdd(&g_cursor[d1.x], 1);
        int p5 = atomicAdd(&g_cursor[d1.y], 1);
        int p6 = atomicAdd(&g_cursor[d1.z], 1);
        int p7 = atomicAdd(&g_cursor[d1.w], 1);
        g_src[d0.x * PAD + p0] = s0.x;
        g_src[d0.y * PAD + p1] = s0.y;
        g_src[d0.z * PAD + p2] = s0.z;
        g_src[d0.w * PAD + p3] = s0.w;
        g_src[d1.x * PAD + p4] = s1.x;
        g_src[d1.y * PAD + p5] = s1.y;
        g_src[d1.z * PAD + p6] = s1.z;
        g_src[d1.w * PAD + p7] = s1.w;
    }
}

// ---------------- layer-1 pre-aggregation (fp8 gathers) ------------------------
__global__ void __launch_bounds__(64) k_agg0() {
    __shared__ int   sidx[PAD];
    __shared__ float swt[PAD];
    int d = blockIdx.x;
    int t = threadIdx.x;
    int cnt = g_cursor[d];
    const int* row = g_src + d * PAD;
    for (int i = t; i < cnt; i += 64) {
        int s = row[i];
        sidx[i] = s;
        swt[i]  = rsqrtf((float)g_cursor[s] + 1.0f);
    }
    __syncthreads();
    float ax = 0.f, ay = 0.f;
    int i = 0;
    for (; i + 4 <= cnt; i += 4) {
        int s0 = sidx[i], s1 = sidx[i + 1], s2 = sidx[i + 2], s3 = sidx[i + 3];
        float w0 = swt[i], w1 = swt[i + 1], w2 = swt[i + 2], w3 = swt[i + 3];
        float2 f0 = fp8x2_to_float2(g_h8[s0 * 64 + t]);
        float2 f1 = fp8x2_to_float2(g_h8[s1 * 64 + t]);
        float2 f2 = fp8x2_to_float2(g_h8[s2 * 64 + t]);
        float2 f3 = fp8x2_to_float2(g_h8[s3 * 64 + t]);
        ax += w0 * f0.x + w1 * f1.x + w2 * f2.x + w3 * f3.x;
        ay += w0 * f0.y + w1 * f1.y + w2 * f2.y + w3 * f3.y;
    }
    for (; i < cnt; i++) {
        int s0 = sidx[i];
        float w0 = swt[i];
        float2 f0 = fp8x2_to_float2(g_h8[s0 * 64 + t]);
        ax += w0 * f0.x;
        ay += w0 * f0.y;
    }
    float dd = rsqrtf((float)cnt + 1.0f);
    float2 hs = fp8x2_to_float2(g_h8[d * 64 + t]);
    float rx = fmaf(dd, ax, dd * dd * hs.x) * (1.0f / HSCALE);
    float ry = fmaf(dd, ay, dd * dd * hs.y) * (1.0f / HSCALE);
    ((__nv_bfloat162*)g_hab)[d * 64 + t] = __floats2bfloat162_rn(rx, ry);
}

// ---------------- mma helpers ---------------------------------------------------
__device__ __forceinline__ void ldmat4(uint32_t* r, const void* p) {
    asm volatile("ldmatrix.sync.aligned.m8n8.x4.shared.b16 {%0,%1,%2,%3}, [%4];"
                 : "=r"(r[0]), "=r"(r[1]), "=r"(r[2]), "=r"(r[3])
                 : "r"(smem_u32(p)));
}

__device__ __forceinline__ void mma16816(float* c, const uint32_t* a, const uint32_t* b) {
    asm volatile("mma.sync.aligned.m16n8k16.row.col.f32.bf16.bf16.f32 "
                 "{%0,%1,%2,%3}, {%4,%5,%6,%7}, {%8,%9}, {%0,%1,%2,%3};"
                 : "+f"(c[0]), "+f"(c[1]), "+f"(c[2]), "+f"(c[3])
                 : "r"(a[0]), "r"(a[1]), "r"(a[2]), "r"(a[3]), "r"(b[0]), "r"(b[1]));
}

__device__ __forceinline__ void mma16832f8(float* c, const uint32_t* a, const uint32_t* b) {
    asm volatile("mma.sync.aligned.m16n8k32.row.col.f32.e4m3.e4m3.f32 "
                 "{%0,%1,%2,%3}, {%4,%5,%6,%7}, {%8,%9}, {%0,%1,%2,%3};"
                 : "+f"(c[0]), "+f"(c[1]), "+f"(c[2]), "+f"(c[3])
                 : "r"(a[0]), "r"(a[1]), "r"(a[2]), "r"(a[3]), "r"(b[0]), "r"(b[1]));
}

__device__ __forceinline__ void cpa16(void* sdst, const void* gsrc) {
    asm volatile("cp.async.cg.shared.global [%0], [%1], 16;"
                 :: "r"(smem_u32(sdst)), "l"(gsrc) : "memory");
}

// ---------------- fused lin: z2 = relu(hab@W1+b1) @ W2, fp8 out ----------------
// grid 128, 256 threads; all operands prefetched via cp.async.
// smem (b16 units): sA1 64x136 | sW1 256x136 | sA2 64x264 | sW2 128x264
static constexpr int LIN_SMEM = (64 * 136 + 256 * 136 + 64 * 264 + 128 * 264) * 2; // 188416

__global__ void __launch_bounds__(256) k_lin(const float* __restrict__ b1) {
    constexpr int P1 = 136, P2 = 264;
    extern __shared__ __nv_bfloat16 smL[];
    __nv_bfloat16* sA1 = smL;
    __nv_bfloat16* sW1 = smL + 64 * P1;
    __nv_bfloat16* sA2 = sW1 + 256 * P1;
    __nv_bfloat16* sW2 = sA2 + 64 * P2;

    int t = threadIdx.x;
    int n0 = blockIdx.x * 64;

    // group 0: hab tile + W1   (phase 1 operands)
    for (int v = t; v < 1024; v += 256) {          // hab: 64 rows x 16 chunks
        int r = v >> 4, m = v & 15;
        cpa16(sA1 + r * P1 + m * 8, g_hab + (size_t)(n0 + r) * FIN + m * 8);
    }
    for (int v = t; v < 4096; v += 256) {          // w1t: 256 rows x 16 chunks
        int r = v >> 4, m = v & 15;
        cpa16(sW1 + r * P1 + m * 8, g_w1t + r * FIN + m * 8);
    }
    asm volatile("cp.async.commit_group;" ::: "memory");
    // group 1: W2 (phase 2 operand), loads overlap phase-1 compute
    for (int v = t; v < 4096; v += 256) {          // w2t: 128 rows x 32 chunks
        int r = v >> 5, m = v & 31;
        cpa16(sW2 + r * P2 + m * 8, g_w2t + r * FH + m * 8);
    }
    asm volatile("cp.async.commit_group;" ::: "memory");

    int lane = t & 31, w = t >> 5;

    // ---- phase 1: a1 = relu(hab @ W1 + b1) -> sA2 (bf16) ----
    asm volatile("cp.async.wait_group 1;" ::: "memory");
    __syncthreads();
    {
        int wm = (w & 1) * 32, wn = (w >> 1) * 64;
        float acc[2][8][4] = {};
#pragma unroll
        for (int ks = 0; ks < 8; ks++) {
            int k0 = ks * 16;
            uint32_t a[2][4], b[8][2];
#pragma unroll
            for (int mt = 0; mt < 2; mt++)
                ldmat4(a[mt], sA1 + (wm + mt * 16 + (lane & 15)) * P1 + k0 + (lane >> 4) * 8);
#pragma unroll
            for (int pr = 0; pr < 4; pr++) {
                uint32_t r4[4];
                ldmat4(r4, sW1 + (wn + pr * 16 + (lane >> 4) * 8 + (lane & 7)) * P1
                             + k0 + ((lane >> 3) & 1) * 8);
                b[2 * pr][0] = r4[0]; b[2 * pr][1] = r4[1];
                b[2 * pr + 1][0] = r4[2]; b[2 * pr + 1][1] = r4[3];
            }
#pragma unroll
            for (int mt = 0; mt < 2; mt++)
#pragma unroll
                for (int nt = 0; nt < 8; nt++) mma16816(acc[mt][nt], a[mt], b[nt]);
        }
#pragma unroll
        for (int mt = 0; mt < 2; mt++) {
            int row = wm + mt * 16 + (lane >> 2);
#pragma unroll
            for (int nt = 0; nt < 8; nt++) {
                int col = wn + nt * 8 + (lane & 3) * 2;
                float2 bb = *(const float2*)(b1 + col);
                float v0 = fmaxf(acc[mt][nt][0] + bb.x, 0.f);
                float v1 = fmaxf(acc[mt][nt][1] + bb.y, 0.f);
                float v2 = fmaxf(acc[mt][nt][2] + bb.x, 0.f);
                float v3 = fmaxf(acc[mt][nt][3] + bb.y, 0.f);
                *(__nv_bfloat162*)&sA2[row * P2 + col]       = __floats2bfloat162_rn(v0, v1);
                *(__nv_bfloat162*)&sA2[(row + 8) * P2 + col] = __floats2bfloat162_rn(v2, v3);
            }
        }
    }
    asm volatile("cp.async.wait_group 0;" ::: "memory");
    __syncthreads();   // a1 visible to all; W2 loaded

    // ---- phase 2: z2 = a1 @ W2 -> fp8 * Z2SCALE ----
    {
        int wm = (w & 1) * 32, wn = (w >> 1) * 32;
        float acc[2][4][4] = {};
#pragma unroll
        for (int ks = 0; ks < 16; ks++) {
            int k0 = ks * 16;
            uint32_t a[2][4], b[4][2];
#pragma unroll
            for (int mt = 0; mt < 2; mt++)
                ldmat4(a[mt], sA2 + (wm + mt * 16 + (lane & 15)) * P2 + k0 + (lane >> 4) * 8);
#pragma unroll
            for (int pr = 0; pr < 2; pr++) {
                uint32_t r4[4];
                ldmat4(r4, sW2 + (wn + pr * 16 + (lane >> 4) * 8 + (lane & 7)) * P2
                             + k0 + ((lane >> 3) & 1) * 8);
                b[2 * pr][0] = r4[0]; b[2 * pr][1] = r4[1];
                b[2 * pr + 1][0] = r4[2]; b[2 * pr + 1][1] = r4[3];
            }
#pragma unroll
            for (int mt = 0; mt < 2; mt++)
#pragma unroll
                for (int nt = 0; nt < 4; nt++) mma16816(acc[mt][nt], a[mt], b[nt]);
        }
#pragma unroll
        for (int mt = 0; mt < 2; mt++) {
            int row = wm + mt * 16 + (lane >> 2);
#pragma unroll
            for (int nt = 0; nt < 4; nt++) {
                int col = wn + nt * 8 + (lane & 3) * 2;
                g_z28[(size_t)(n0 + row) * 64 + (col >> 1)] =
                    float2_to_fp8x2(acc[mt][nt][0] * Z2SCALE, acc[mt][nt][1] * Z2SCALE);
                g_z28[(size_t)(n0 + row + 8) * 64 + (col >> 1)] =
                    float2_to_fp8x2(acc[mt][nt][2] * Z2SCALE, acc[mt][nt][3] * Z2SCALE);
            }
        }
    }
}

// ---------------- GCN aggregation, layer 2 (fp8 gathers) -> fp8 z ---------------
__global__ void __launch_bounds__(64) k_agg2(const float* __restrict__ bias) {
    __shared__ int   sidx[PAD];
    __shared__ float swt[PAD];
    int d = blockIdx.x;
    int t = threadIdx.x;
    int cnt = g_cursor[d];
    const int* row = g_src + d * PAD;
    for (int i = t; i < cnt; i += 64) {
        int s = row[i];
        sidx[i] = s;
        swt[i]  = rsqrtf((float)g_cursor[s] + 1.0f);
    }
    __syncthreads();
    float ax = 0.f, ay = 0.f;
    int i = 0;
    for (; i + 4 <= cnt; i += 4) {
        int s0 = sidx[i], s1 = sidx[i + 1], s2 = sidx[i + 2], s3 = sidx[i + 3];
        float w0 = swt[i], w1 = swt[i + 1], w2 = swt[i + 2], w3 = swt[i + 3];
        float2 f0 = fp8x2_to_float2(g_z28[s0 * 64 + t]);
        float2 f1 = fp8x2_to_float2(g_z28[s1 * 64 + t]);
        float2 f2 = fp8x2_to_float2(g_z28[s2 * 64 + t]);
        float2 f3 = fp8x2_to_float2(g_z28[s3 * 64 + t]);
        ax += w0 * f0.x + w1 * f1.x + w2 * f2.x + w3 * f3.x;
        ay += w0 * f0.y + w1 * f1.y + w2 * f2.y + w3 * f3.y;
    }
    for (; i < cnt; i++) {
        int s0 = sidx[i];
        float w0 = swt[i];
        float2 f0 = fp8x2_to_float2(g_z28[s0 * 64 + t]);
        ax += w0 * f0.x;
        ay += w0 * f0.y;
    }
    float dd = rsqrtf((float)cnt + 1.0f);
    float2 zs = fp8x2_to_float2(g_z28[d * 64 + t]);
    float2 bb = ((const float2*)bias)[t];
    // (agg/Z2SCALE + b) * ZSCALE
    float rx = fmaf(fmaf(dd, ax, dd * dd * zs.x), ZSCALE / Z2SCALE, bb.x * ZSCALE);
    float ry = fmaf(fmaf(dd, ay, dd * dd * zs.y), ZSCALE / Z2SCALE, bb.y * ZSCALE);
    g_z8[d * 64 + t] = float2_to_fp8x2(rx, ry);
}

// ---------------- decode: persistent fp8 mma, occ 2 -----------------------------
__device__ __forceinline__ float sigmoidf_(float v) {
    float th;
    asm("tanh.approx.f32 %0, %1;" : "=f"(th) : "f"(v * SIGSCALE));
    return fmaf(th, 0.5f, 0.5f);
}

__device__ __forceinline__ void bulk_store_row(void* gptr, uint32_t saddr, int bytes) {
    asm volatile("cp.async.bulk.global.shared::cta.bulk_group [%0], [%1], %2;"
                 :: "l"(gptr), "r"(saddr), "r"(bytes) : "memory");
}

__device__ __forceinline__ void tile_coords(int idx, int& bi, int& bj) {
    float fb = 64.5f - sqrtf(64.5f * 64.5f - 2.0f * (float)idx);
    int b = (int)fb;
    if (b < 0) b = 0;
    while (b > 0 && (b * 64 - b * (b - 1) / 2) > idx) b--;
    while (((b + 1) * 64 - (b + 1) * b / 2) <= idx) b++;
    bi = b;
    bj = b + (idx - (b * 64 - b * (b - 1) / 2));
}

static constexpr int STG_SZ   = 128 * 136 * 4;      // 69632
static constexpr int ZB_OFF   = STG_SZ;
static constexpr int ZT_SZ    = 128 * 144;          // 18432
static constexpr int DEC_SMEM = STG_SZ + 2 * ZT_SZ; // 106496 -> 2 CTAs/SM

__global__ void __launch_bounds__(256, 2) k_decode(float* __restrict__ out) {
    extern __shared__ char smb[];
    int t = threadIdx.x;
    int lane = t & 31, w = t >> 5;
    int wm = (w & 3) * 32;
    int wn = (w >> 2) * 64;
    constexpr int PU = 72;
    constexpr int PF = 136;

    if (blockIdx.x < 32) g_cursor[blockIdx.x * 256 + t] = 0;

    float* sf = (float*)smb;
    const __nv_bfloat16* zA = (const __nv_bfloat16*)(smb + ZB_OFF);
    const __nv_bfloat16* zB = zA + ZT_SZ / 2;

    for (int idx = blockIdx.x; idx < NTILES; idx += DGRID) {
        int bi, bj;
        tile_coords(idx, bi, bj);
        int i0 = bi * 128, j0 = bj * 128;
        bool diag = (bi == bj);

        {
            const char* Z = (const char*)g_z8;
#pragma unroll
            for (int k = 0; k < 8; k++) {
                int v = t + k * 256;
                int which = v >> 10;
                int r = (v >> 3) & 127;
                int c = (v & 7) * 16;
                const char* srcp = Z + (((size_t)((which ? j0 : i0) + r)) << 7) + c;
                uint32_t dstp = smem_u32(smb + ZB_OFF + which * ZT_SZ + r * 144 + c);
                asm volatile("cp.async.cg.shared.global [%0], [%1], 16;"
                             :: "r"(dstp), "l"(srcp) : "memory");
            }
        }
        asm volatile("cp.async.commit_group;" ::: "memory");
        asm volatile("cp.async.wait_group 0;" ::: "memory");
        __syncthreads();

        float acc[2][8][4] = {};
#pragma unroll
        for (int ks = 0; ks < 4; ks++) {
            int k0 = ks * 16;
            uint32_t a[2][4], b[8][2];
#pragma unroll
            for (int mt = 0; mt < 2; mt++)
                ldmat4(a[mt], zA + (wm + mt * 16 + (lane & 15)) * PU + k0 + (lane >> 4) * 8);
#pragma unroll
            for (int pr = 0; pr < 4; pr++) {
                uint32_t r4[4];
                ldmat4(r4, zB + (wn + pr * 16 + (lane >> 4) * 8 + (lane & 7)) * PU
                             + k0 + ((lane >> 3) & 1) * 8);
                b[2 * pr][0] = r4[0]; b[2 * pr][1] = r4[1];
                b[2 * pr + 1][0] = r4[2]; b[2 * pr + 1][1] = r4[3];
            }
#pragma unroll
            for (int mt = 0; mt < 2; mt++)
#pragma unroll
                for (int nt = 0; nt < 8; nt++) mma16832f8(acc[mt][nt], a[mt], b[nt]);
        }

#pragma unroll
        for (int mt = 0; mt < 2; mt++)
#pragma unroll
            for (int nt = 0; nt < 8; nt++)
#pragma unroll
                for (int q = 0; q < 4; q++) acc[mt][nt][q] = sigmoidf_(acc[mt][nt][q]);

        int r0b = wm + (lane >> 2);

        // pass 1: direct tile
        asm volatile("cp.async.bulk.wait_group.read 0;" ::: "memory");
        __syncthreads();
#pragma unroll
        for (int mt = 0; mt < 2; mt++) {
            int r0 = r0b + mt * 16;
#pragma unroll
            for (int nt = 0; nt < 8; nt++) {
                int c0 = wn + nt * 8 + (lane & 3) * 2;
                *(float2*)&sf[r0 * PF + c0] =
                    make_float2(acc[mt][nt][0], acc[mt][nt][1]);
                *(float2*)&sf[(r0 + 8) * PF + c0] =
                    make_float2(acc[mt][nt][2], acc[mt][nt][3]);
            }
        }
        __syncthreads();
        if (t < 128) {
            asm volatile("fence.proxy.async.shared::cta;" ::: "memory");
            bulk_store_row(out + (size_t)(i0 + t) * NN + j0, smem_u32(&sf[t * PF]), 512);
            asm volatile("cp.async.bulk.commit_group;" ::: "memory");
        }

        // pass 2: mirror tile (transposed)
        if (!diag) {
            asm volatile("cp.async.bulk.wait_group.read 0;" ::: "memory");
            __syncthreads();
#pragma unroll
            for (int mt = 0; mt < 2; mt++) {
                int r0 = r0b + mt * 16;
#pragma unroll
                for (int nt = 0; nt < 8; nt++) {
                    int c0 = wn + nt * 8 + (lane & 3) * 2;
                    sf[c0 * PF + r0]           = acc[mt][nt][0];
                    sf[(c0 + 1) * PF + r0]     = acc[mt][nt][1];
                    sf[c0 * PF + r0 + 8]       = acc[mt][nt][2];
                    sf[(c0 + 1) * PF + r0 + 8] = acc[mt][nt][3];
                }
            }
            __syncthreads();
            if (t < 128) {
                asm volatile("fence.proxy.async.shared::cta;" ::: "memory");
                bulk_store_row(out + (size_t)(j0 + t) * NN + i0, smem_u32(&sf[t * PF]), 512);
                asm volatile("cp.async.bulk.commit_group;" ::: "memory");
            }
        }
    }

    asm volatile("cp.async.bulk.wait_group 0;" ::: "memory");
}

// ---------------- launch ----------------------------------------------------------
extern "C" void kernel_launch(void* const* d_in, const int* in_sizes, int n_in,
                              void* d_out, int out_size) {
    const int*   x   = (const int*)d_in[0];
    const int*   ei  = (const int*)d_in[1];
    const float* emb = (const float*)d_in[2];
    const float* W1  = (const float*)d_in[3];
    const float* b1  = (const float*)d_in[4];
    const float* W2  = (const float*)d_in[5];
    const float* b2  = (const float*)d_in[6];
    float* out = (float*)d_out;

    const int* src = ei;
    const int* dst = ei + EE;

    cudaFuncSetAttribute(k_decode, cudaFuncAttributeMaxDynamicSharedMemorySize, DEC_SMEM);
    cudaFuncSetAttribute(k_lin,    cudaFuncAttributeMaxDynamicSharedMemorySize, LIN_SMEM);

    k_prep<<<2560, 256>>>(x, emb, W1, W2, src, dst);
    k_agg0<<<NN, 64>>>();
    k_lin <<<NN / 64, 256, LIN_SMEM>>>(b1);
    k_agg2<<<NN, 64>>>(b2);
    k_decode<<<DGRID, 256, DEC_SMEM>>>(out);
}

// round 11
// speedup vs baseline: 1.4063x; 1.1019x over previous
#include <cuda_runtime.h>
#include <cuda_bf16.h>
#include <cuda_fp16.h>
#include <cstdint>

static constexpr int NN  = 8192;
static constexpr int EE  = 524288;
static constexpr int FIN = 128;
static constexpr int FH  = 256;
static constexpr int FO  = 128;
static constexpr int PAD = 192;   // padded CSR row stride (max degree ~98)

static constexpr int NT128  = NN / 128;
static constexpr int NTILES = NT128 * (NT128 + 1) / 2;  // 2080
static constexpr int DGRID  = 304;                      // 2 CTAs / SM

static constexpr float HSCALE  = 512.0f;    // h  stored as e4m3 * 512
static constexpr float Z2SCALE = 4096.0f;   // z2 stored as e4m3 * 4096
static constexpr float ZSCALE  = 256.0f;    // z  stored as e4m3 * 256
static constexpr float SIGSCALE = 0.5f / (ZSCALE * ZSCALE);

// ---------------- scratch ----------------------------------------------------
__device__ int g_cursor[NN];       // degree counter; reset by k_decode each run
__device__ int g_src[NN * PAD];
__device__ __nv_bfloat16 g_w1t[FH * FIN];
__device__ __nv_bfloat16 g_w2t[FO * FH];
__device__ uint16_t      g_h8[NN * 64];    // h  as e4m3 pairs (*HSCALE)
__device__ __nv_bfloat16 g_hab[NN * FIN];  // aggregated h (bf16)
__device__ uint16_t      g_z28[NN * 64];   // z2 as e4m3 pairs (*Z2SCALE)
__device__ uint16_t      g_z8[NN * 64];    // z  as e4m3 pairs (*ZSCALE)

// ---------------- helpers ------------------------------------------------------
__device__ __forceinline__ uint32_t smem_u32(const void* p) {
    return (uint32_t)__cvta_generic_to_shared(p);
}

__device__ __forceinline__ float2 fp8x2_to_float2(uint16_t pk) {
    uint32_t h2;
    asm("cvt.rn.f16x2.e4m3x2 %0, %1;" : "=r"(h2) : "h"(pk));
    __half2 hh = *reinterpret_cast<__half2*>(&h2);
    return __half22float2(hh);
}

__device__ __forceinline__ uint16_t float2_to_fp8x2(float lo, float hi) {
    uint16_t pk;
    asm("cvt.rn.satfinite.e4m3x2.f32 %0, %1, %2;" : "=h"(pk) : "f"(hi), "f"(lo));
    return pk;
}

// 4 fp8 (uint32) -> two f16x2
__device__ __forceinline__ void fp8x4_to_h2x2(uint32_t v, uint32_t& lo2, uint32_t& hi2) {
    asm("{ .reg .b16 lo, hi;\n\t"
        "mov.b32 {lo, hi}, %2;\n\t"
        "cvt.rn.f16x2.e4m3x2 %0, lo;\n\t"
        "cvt.rn.f16x2.e4m3x2 %1, hi; }"
        : "=r"(lo2), "=r"(hi2) : "r"(v));
}

// ---------------- fused prep: wconv | gather(fp8) | CSR fill -------------------
__global__ void k_prep(const int* __restrict__ x, const float* __restrict__ emb,
                       const float* __restrict__ W1, const float* __restrict__ W2,
                       const int* __restrict__ src, const int* __restrict__ dst) {
    int b = blockIdx.x;
    if (b < 2048) {                       // embedding gather -> fp8*HSCALE
        int idx = b * 256 + threadIdx.x;
        int n = idx >> 6, t = idx & 63;
        float2 f = *(const float2*)(emb + (size_t)x[n] * FIN + t * 2);
        g_h8[n * 64 + t] = float2_to_fp8x2(f.x * HSCALE, f.y * HSCALE);
    } else if (b < 2048 + 256) {          // weight transpose + bf16
        int idx = (b - 2048) * 256 + threadIdx.x;
        if (idx < FH * FIN) {
            int j = idx >> 7, k = idx & 127;
            g_w1t[idx] = __float2bfloat16(W1[k * FH + j]);
        } else {
            int i2 = idx - FH * FIN;
            int j = i2 >> 8, k = i2 & 255;
            g_w2t[i2] = __float2bfloat16(W2[k * FO + j]);
        }
    } else {                              // padded CSR fill, 8 edges/thread
        int e = ((b - 2304) * 256 + threadIdx.x) * 8;
        int4 d0 = *(const int4*)(dst + e);
        int4 d1 = *(const int4*)(dst + e + 4);
        int4 s0 = *(const int4*)(src + e);
        int4 s1 = *(const int4*)(src + e + 4);
        int p0 = atomicAdd(&g_cursor[d0.x], 1);
        int p1 = atomicAdd(&g_cursor[d0.y], 1);
        int p2 = atomicAdd(&g_cursor[d0.z], 1);
        int p3 = atomicAdd(&g_cursor[d0.w], 1);
        int p4 = atomicAdd(&g_cursor[d1.x], 1);
        int p5 = atomicAdd(&g_cursor[d1.y], 1);
        int p6 = atomicAdd(&g_cursor[d1.z], 1);
        int p7 = atomicAdd(&g_cursor[d1.w], 1);
        g_src[d0.x * PAD + p0] = s0.x;
        g_src[d0.y * PAD + p1] = s0.y;
        g_src[d0.z * PAD + p2] = s0.z;
        g_src[d0.w * PAD + p3] = s0.w;
        g_src[d1.x * PAD + p4] = s1.x;
        g_src[d1.y * PAD + p5] = s1.y;
        g_src[d1.z * PAD + p6] = s1.z;
        g_src[d1.w * PAD + p7] = s1.w;
    }
}

// ---------------- aggregation core: 32 threads, 4 feats/thread, HFMA2 ----------
// IN8: fp8 matrix [NN][32] uint32 rows. Accumulates sum_s w_s * IN[s] in f16x2.
// Returns 4 f32 values (features 4t..4t+3) plus count via refs.
template <typename EPI>
__device__ __forceinline__ void agg_core(const uint32_t* __restrict__ IN,
                                         int d, int t, EPI epi) {
    __shared__ int      sidx[PAD];
    __shared__ uint32_t swt2[PAD];   // half2(w, w)
    int cnt = g_cursor[d];
    const int* row = g_src + d * PAD;
    for (int i = t; i < cnt; i += 32) {
        int s = row[i];
        sidx[i] = s;
        __half2 hw = __float2half2_rn(rsqrtf((float)g_cursor[s] + 1.0f));
        swt2[i] = *(uint32_t*)&hw;
    }
    __syncwarp();

    __half2 accA = __float2half2_rn(0.f), accB = __float2half2_rn(0.f);
    __half2 accC = __float2half2_rn(0.f), accD = __float2half2_rn(0.f);
    int i = 0;
    for (; i + 4 <= cnt; i += 4) {
        int s0 = sidx[i], s1 = sidx[i + 1], s2 = sidx[i + 2], s3 = sidx[i + 3];
        uint32_t v0 = IN[s0 * 32 + t];
        uint32_t v1 = IN[s1 * 32 + t];
        uint32_t v2 = IN[s2 * 32 + t];
        uint32_t v3 = IN[s3 * 32 + t];
        uint32_t w0 = swt2[i], w1 = swt2[i + 1], w2 = swt2[i + 2], w3 = swt2[i + 3];
        uint32_t l0, h0, l1, h1, l2, h2, l3, h3;
        fp8x4_to_h2x2(v0, l0, h0);
        fp8x4_to_h2x2(v1, l1, h1);
        fp8x4_to_h2x2(v2, l2, h2);
        fp8x4_to_h2x2(v3, l3, h3);
        accA = __hfma2(*(__half2*)&w0, *(__half2*)&l0, accA);
        accB = __hfma2(*(__half2*)&w0, *(__half2*)&h0, accB);
        accC = __hfma2(*(__half2*)&w1, *(__half2*)&l1, accC);
        accD = __hfma2(*(__half2*)&w1, *(__half2*)&h1, accD);
        accA = __hfma2(*(__half2*)&w2, *(__half2*)&l2, accA);
        accB = __hfma2(*(__half2*)&w2, *(__half2*)&h2, accB);
        accC = __hfma2(*(__half2*)&w3, *(__half2*)&l3, accC);
        accD = __hfma2(*(__half2*)&w3, *(__half2*)&h3, accD);
    }
    for (; i < cnt; i++) {
        int s0 = sidx[i];
        uint32_t v0 = IN[s0 * 32 + t];
        uint32_t w0 = swt2[i];
        uint32_t l0, h0;
        fp8x4_to_h2x2(v0, l0, h0);
        accA = __hfma2(*(__half2*)&w0, *(__half2*)&l0, accA);
        accB = __hfma2(*(__half2*)&w0, *(__half2*)&h0, accB);
    }
    float2 sAB0 = __half22float2(__hadd2(accA, accC));
    float2 sAB1 = __half22float2(__hadd2(accB, accD));

    // self term in f32
    float dd = rsqrtf((float)cnt + 1.0f);
    uint32_t vs = IN[d * 32 + t];
    uint32_t ls, hs;
    fp8x4_to_h2x2(vs, ls, hs);
    float2 f01 = __half22float2(*(__half2*)&ls);
    float2 f23 = __half22float2(*(__half2*)&hs);
    float r0 = fmaf(dd, sAB0.x, dd * dd * f01.x);
    float r1 = fmaf(dd, sAB0.y, dd * dd * f01.y);
    float r2 = fmaf(dd, sAB1.x, dd * dd * f23.x);
    float r3 = fmaf(dd, sAB1.y, dd * dd * f23.y);
    epi(r0, r1, r2, r3);
}

// layer-1 pre-aggregation: out bf16 g_hab (descale by HSCALE)
__global__ void __launch_bounds__(32) k_agg0() {
    int d = blockIdx.x;
    int t = threadIdx.x;
    agg_core((const uint32_t*)g_h8, d, t, [&](float r0, float r1, float r2, float r3) {
        constexpr float inv = 1.0f / HSCALE;
        __nv_bfloat162 b0 = __floats2bfloat162_rn(r0 * inv, r1 * inv);
        __nv_bfloat162 b1 = __floats2bfloat162_rn(r2 * inv, r3 * inv);
        *(uint2*)&g_hab[(size_t)d * FIN + t * 4] =
            make_uint2(*(uint32_t*)&b0, *(uint32_t*)&b1);
    });
}

// layer-2 aggregation: in g_z28 (*Z2SCALE), + bias, out g_z8 (*ZSCALE)
__global__ void __launch_bounds__(32) k_agg2(const float* __restrict__ bias) {
    int d = blockIdx.x;
    int t = threadIdx.x;
    float4 bb = *(const float4*)(bias + t * 4);
    agg_core((const uint32_t*)g_z28, d, t, [&](float r0, float r1, float r2, float r3) {
        constexpr float k = ZSCALE / Z2SCALE;
        float o0 = fmaf(r0, k, bb.x * ZSCALE);
        float o1 = fmaf(r1, k, bb.y * ZSCALE);
        float o2 = fmaf(r2, k, bb.z * ZSCALE);
        float o3 = fmaf(r3, k, bb.w * ZSCALE);
        uint16_t p0 = float2_to_fp8x2(o0, o1);
        uint16_t p1 = float2_to_fp8x2(o2, o3);
        ((uint32_t*)g_z8)[d * 32 + t] = (uint32_t)p0 | ((uint32_t)p1 << 16);
    });
}

// ---------------- mma helpers ---------------------------------------------------
__device__ __forceinline__ void ldmat4(uint32_t* r, const void* p) {
    asm volatile("ldmatrix.sync.aligned.m8n8.x4.shared.b16 {%0,%1,%2,%3}, [%4];"
                 : "=r"(r[0]), "=r"(r[1]), "=r"(r[2]), "=r"(r[3])
                 : "r"(smem_u32(p)));
}

__device__ __forceinline__ void mma16816(float* c, const uint32_t* a, const uint32_t* b) {
    asm volatile("mma.sync.aligned.m16n8k16.row.col.f32.bf16.bf16.f32 "
                 "{%0,%1,%2,%3}, {%4,%5,%6,%7}, {%8,%9}, {%0,%1,%2,%3};"
                 : "+f"(c[0]), "+f"(c[1]), "+f"(c[2]), "+f"(c[3])
                 : "r"(a[0]), "r"(a[1]), "r"(a[2]), "r"(a[3]), "r"(b[0]), "r"(b[1]));
}

__device__ __forceinline__ void mma16832f8(float* c, const uint32_t* a, const uint32_t* b) {
    asm volatile("mma.sync.aligned.m16n8k32.row.col.f32.e4m3.e4m3.f32 "
                 "{%0,%1,%2,%3}, {%4,%5,%6,%7}, {%8,%9}, {%0,%1,%2,%3};"
                 : "+f"(c[0]), "+f"(c[1]), "+f"(c[2]), "+f"(c[3])
                 : "r"(a[0]), "r"(a[1]), "r"(a[2]), "r"(a[3]), "r"(b[0]), "r"(b[1]));
}

__device__ __forceinline__ void cpa16(void* sdst, const void* gsrc) {
    asm volatile("cp.async.cg.shared.global [%0], [%1], 16;"
                 :: "r"(smem_u32(sdst)), "l"(gsrc) : "memory");
}

// ---------------- fused lin: z2 = relu(hab@W1+b1) @ W2, fp8 out ----------------
static constexpr int LIN_SMEM = (64 * 136 + 256 * 136 + 64 * 264 + 128 * 264) * 2; // 188416

__global__ void __launch_bounds__(256) k_lin(const float* __restrict__ b1) {
    constexpr int P1 = 136, P2 = 264;
    extern __shared__ __nv_bfloat16 smL[];
    __nv_bfloat16* sA1 = smL;
    __nv_bfloat16* sW1 = smL + 64 * P1;
    __nv_bfloat16* sA2 = sW1 + 256 * P1;
    __nv_bfloat16* sW2 = sA2 + 64 * P2;

    int t = threadIdx.x;
    int n0 = blockIdx.x * 64;

    for (int v = t; v < 1024; v += 256) {
        int r = v >> 4, m = v & 15;
        cpa16(sA1 + r * P1 + m * 8, g_hab + (size_t)(n0 + r) * FIN + m * 8);
    }
    for (int v = t; v < 4096; v += 256) {
        int r = v >> 4, m = v & 15;
        cpa16(sW1 + r * P1 + m * 8, g_w1t + r * FIN + m * 8);
    }
    asm volatile("cp.async.commit_group;" ::: "memory");
    for (int v = t; v < 4096; v += 256) {
        int r = v >> 5, m = v & 31;
        cpa16(sW2 + r * P2 + m * 8, g_w2t + r * FH + m * 8);
    }
    asm volatile("cp.async.commit_group;" ::: "memory");

    int lane = t & 31, w = t >> 5;

    asm volatile("cp.async.wait_group 1;" ::: "memory");
    __syncthreads();
    {
        int wm = (w & 1) * 32, wn = (w >> 1) * 64;
        float acc[2][8][4] = {};
#pragma unroll
        for (int ks = 0; ks < 8; ks++) {
            int k0 = ks * 16;
            uint32_t a[2][4], b[8][2];
#pragma unroll
            for (int mt = 0; mt < 2; mt++)
                ldmat4(a[mt], sA1 + (wm + mt * 16 + (lane & 15)) * P1 + k0 + (lane >> 4) * 8);
#pragma unroll
            for (int pr = 0; pr < 4; pr++) {
                uint32_t r4[4];
                ldmat4(r4, sW1 + (wn + pr * 16 + (lane >> 4) * 8 + (lane & 7)) * P1
                             + k0 + ((lane >> 3) & 1) * 8);
                b[2 * pr][0] = r4[0]; b[2 * pr][1] = r4[1];
                b[2 * pr + 1][0] = r4[2]; b[2 * pr + 1][1] = r4[3];
            }
#pragma unroll
            for (int mt = 0; mt < 2; mt++)
#pragma unroll
                for (int nt = 0; nt < 8; nt++) mma16816(acc[mt][nt], a[mt], b[nt]);
        }
#pragma unroll
        for (int mt = 0; mt < 2; mt++) {
            int row = wm + mt * 16 + (lane >> 2);
#pragma unroll
            for (int nt = 0; nt < 8; nt++) {
                int col = wn + nt * 8 + (lane & 3) * 2;
                float2 bb = *(const float2*)(b1 + col);
                float v0 = fmaxf(acc[mt][nt][0] + bb.x, 0.f);
                float v1 = fmaxf(acc[mt][nt][1] + bb.y, 0.f);
                float v2 = fmaxf(acc[mt][nt][2] + bb.x, 0.f);
                float v3 = fmaxf(acc[mt][nt][3] + bb.y, 0.f);
                *(__nv_bfloat162*)&sA2[row * P2 + col]       = __floats2bfloat162_rn(v0, v1);
                *(__nv_bfloat162*)&sA2[(row + 8) * P2 + col] = __floats2bfloat162_rn(v2, v3);
            }
        }
    }
    asm volatile("cp.async.wait_group 0;" ::: "memory");
    __syncthreads();

    {
        int wm = (w & 1) * 32, wn = (w >> 1) * 32;
        float acc[2][4][4] = {};
#pragma unroll
        for (int ks = 0; ks < 16; ks++) {
            int k0 = ks * 16;
            uint32_t a[2][4], b[4][2];
#pragma unroll
            for (int mt = 0; mt < 2; mt++)
                ldmat4(a[mt], sA2 + (wm + mt * 16 + (lane & 15)) * P2 + k0 + (lane >> 4) * 8);
#pragma unroll
            for (int pr = 0; pr < 2; pr++) {
                uint32_t r4[4];
                ldmat4(r4, sW2 + (wn + pr * 16 + (lane >> 4) * 8 + (lane & 7)) * P2
                             + k0 + ((lane >> 3) & 1) * 8);
                b[2 * pr][0] = r4[0]; b[2 * pr][1] = r4[1];
                b[2 * pr + 1][0] = r4[2]; b[2 * pr + 1][1] = r4[3];
            }
#pragma unroll
            for (int mt = 0; mt < 2; mt++)
#pragma unroll
                for (int nt = 0; nt < 4; nt++) mma16816(acc[mt][nt], a[mt], b[nt]);
        }
#pragma unroll
        for (int mt = 0; mt < 2; mt++) {
            int row = wm + mt * 16 + (lane >> 2);
#pragma unroll
            for (int nt = 0; nt < 4; nt++) {
                int col = wn + nt * 8 + (lane & 3) * 2;
                g_z28[(size_t)(n0 + row) * 64 + (col >> 1)] =
                    float2_to_fp8x2(acc[mt][nt][0] * Z2SCALE, acc[mt][nt][1] * Z2SCALE);
                g_z28[(size_t)(n0 + row + 8) * 64 + (col >> 1)] =
                    float2_to_fp8x2(acc[mt][nt][2] * Z2SCALE, acc[mt][nt][3] * Z2SCALE);
            }
        }
    }
}

// ---------------- decode: persistent fp8 mma, occ 2 -----------------------------
__device__ __forceinline__ float sigmoidf_(float v) {
    float th;
    asm("tanh.approx.f32 %0, %1;" : "=f"(th) : "f"(v * SIGSCALE));
    return fmaf(th, 0.5f, 0.5f);
}

__device__ __forceinline__ void bulk_store_row(void* gptr, uint32_t saddr, int bytes) {
    asm volatile("cp.async.bulk.global.shared::cta.bulk_group [%0], [%1], %2;"
                 :: "l"(gptr), "r"(saddr), "r"(bytes) : "memory");
}

__device__ __forceinline__ void tile_coords(int idx, int& bi, int& bj) {
    float fb = 64.5f - sqrtf(64.5f * 64.5f - 2.0f * (float)idx);
    int b = (int)fb;
    if (b < 0) b = 0;
    while (b > 0 && (b * 64 - b * (b - 1) / 2) > idx) b--;
    while (((b + 1) * 64 - (b + 1) * b / 2) <= idx) b++;
    bi = b;
    bj = b + (idx - (b * 64 - b * (b - 1) / 2));
}

static constexpr int STG_SZ   = 128 * 136 * 4;      // 69632
static constexpr int ZB_OFF   = STG_SZ;
static constexpr int ZT_SZ    = 128 * 144;          // 18432
static constexpr int DEC_SMEM = STG_SZ + 2 * ZT_SZ; // 106496 -> 2 CTAs/SM

__global__ void __launch_bounds__(256, 2) k_decode(float* __restrict__ out) {
    extern __shared__ char smb[];
    int t = threadIdx.x;
    int lane = t & 31, w = t >> 5;
    int wm = (w & 3) * 32;
    int wn = (w >> 2) * 64;
    constexpr int PU = 72;
    constexpr int PF = 136;

    if (blockIdx.x < 32) g_cursor[blockIdx.x * 256 + t] = 0;

    float* sf = (float*)smb;
    const __nv_bfloat16* zA = (const __nv_bfloat16*)(smb + ZB_OFF);
    const __nv_bfloat16* zB = zA + ZT_SZ / 2;

    for (int idx = blockIdx.x; idx < NTILES; idx += DGRID) {
        int bi, bj;
        tile_coords(idx, bi, bj);
        int i0 = bi * 128, j0 = bj * 128;
        bool diag = (bi == bj);

        {
            const char* Z = (const char*)g_z8;
#pragma unroll
            for (int k = 0; k < 8; k++) {
                int v = t + k * 256;
                int which = v >> 10;
                int r = (v >> 3) & 127;
                int c = (v & 7) * 16;
                const char* srcp = Z + (((size_t)((which ? j0 : i0) + r)) << 7) + c;
                uint32_t dstp = smem_u32(smb + ZB_OFF + which * ZT_SZ + r * 144 + c);
                asm volatile("cp.async.cg.shared.global [%0], [%1], 16;"
                             :: "r"(dstp), "l"(srcp) : "memory");
            }
        }
        asm volatile("cp.async.commit_group;" ::: "memory");
        asm volatile("cp.async.wait_group 0;" ::: "memory");
        __syncthreads();

        float acc[2][8][4] = {};
#pragma unroll
        for (int ks = 0; ks < 4; ks++) {
            int k0 = ks * 16;
            uint32_t a[2][4], b[8][2];
#pragma unroll
            for (int mt = 0; mt < 2; mt++)
                ldmat4(a[mt], zA + (wm + mt * 16 + (lane & 15)) * PU + k0 + (lane >> 4) * 8);
#pragma unroll
            for (int pr = 0; pr < 4; pr++) {
                uint32_t r4[4];
                ldmat4(r4, zB + (wn + pr * 16 + (lane >> 4) * 8 + (lane & 7)) * PU
                             + k0 + ((lane >> 3) & 1) * 8);
                b[2 * pr][0] = r4[0]; b[2 * pr][1] = r4[1];
                b[2 * pr + 1][0] = r4[2]; b[2 * pr + 1][1] = r4[3];
            }
#pragma unroll
            for (int mt = 0; mt < 2; mt++)
#pragma unroll
                for (int nt = 0; nt < 8; nt++) mma16832f8(acc[mt][nt], a[mt], b[nt]);
        }

#pragma unroll
        for (int mt = 0; mt < 2; mt++)
#pragma unroll
            for (int nt = 0; nt < 8; nt++)
#pragma unroll
                for (int q = 0; q < 4; q++) acc[mt][nt][q] = sigmoidf_(acc[mt][nt][q]);

        int r0b = wm + (lane >> 2);

        // pass 1: direct tile
        asm volatile("cp.async.bulk.wait_group.read 0;" ::: "memory");
        __syncthreads();
#pragma unroll
        for (int mt = 0; mt < 2; mt++) {
            int r0 = r0b + mt * 16;
#pragma unroll
            for (int nt = 0; nt < 8; nt++) {
                int c0 = wn + nt * 8 + (lane & 3) * 2;
                *(float2*)&sf[r0 * PF + c0] =
                    make_float2(acc[mt][nt][0], acc[mt][nt][1]);
                *(float2*)&sf[(r0 + 8) * PF + c0] =
                    make_float2(acc[mt][nt][2], acc[mt][nt][3]);
            }
        }
        __syncthreads();
        if (t < 128) {
            asm volatile("fence.proxy.async.shared::cta;" ::: "memory");
            bulk_store_row(out + (size_t)(i0 + t) * NN + j0, smem_u32(&sf[t * PF]), 512);
            asm volatile("cp.async.bulk.commit_group;" ::: "memory");
        }

        // pass 2: mirror tile (transposed)
        if (!diag) {
            asm volatile("cp.async.bulk.wait_group.read 0;" ::: "memory");
            __syncthreads();
#pragma unroll
            for (int mt = 0; mt < 2; mt++) {
                int r0 = r0b + mt * 16;
#pragma unroll
                for (int nt = 0; nt < 8; nt++) {
                    int c0 = wn + nt * 8 + (lane & 3) * 2;
                    sf[c0 * PF + r0]           = acc[mt][nt][0];
                    sf[(c0 + 1) * PF + r0]     = acc[mt][nt][1];
                    sf[c0 * PF + r0 + 8]       = acc[mt][nt][2];
                    sf[(c0 + 1) * PF + r0 + 8] = acc[mt][nt][3];
                }
            }
            __syncthreads();
            if (t < 128) {
                asm volatile("fence.proxy.async.shared::cta;" ::: "memory");
                bulk_store_row(out + (size_t)(j0 + t) * NN + i0, smem_u32(&sf[t * PF]), 512);
                asm volatile("cp.async.bulk.commit_group;" ::: "memory");
            }
        }
    }

    asm volatile("cp.async.bulk.wait_group 0;" ::: "memory");
}

// ---------------- launch ----------------------------------------------------------
extern "C" void kernel_launch(void* const* d_in, const int* in_sizes, int n_in,
                              void* d_out, int out_size) {
    const int*   x   = (const int*)d_in[0];
    const int*   ei  = (const int*)d_in[1];
    const float* emb = (const float*)d_in[2];
    const float* W1  = (const float*)d_in[3];
    const float* b1  = (const float*)d_in[4];
    const float* W2  = (const float*)d_in[5];
    const float* b2  = (const float*)d_in[6];
    float* out = (float*)d_out;

    const int* src = ei;
    const int* dst = ei + EE;

    cudaFuncSetAttribute(k_decode, cudaFuncAttributeMaxDynamicSharedMemorySize, DEC_SMEM);
    cudaFuncSetAttribute(k_lin,    cudaFuncAttributeMaxDynamicSharedMemorySize, LIN_SMEM);

    k_prep<<<2560, 256>>>(x, emb, W1, W2, src, dst);
    k_agg0<<<NN, 32>>>();
    k_lin <<<NN / 64, 256, LIN_SMEM>>>(b1);
    k_agg2<<<NN, 32>>>(b2);
    k_decode<<<DGRID, 256, DEC_SMEM>>>(out);
}